// round 1
// baseline (speedup 1.0000x reference)
#include <cuda_runtime.h>
#include <math.h>

#define BS   2
#define LEN  11253
#define MROWS (BS*LEN)   // 22506
#define D    256
#define NH   8
#define NP   4
#define NL   4
#define DH   32
#define DFF  1024

// ---- scratch (device globals; no allocation allowed) ----
__device__ float g_value  [(size_t)MROWS * D];
__device__ float g_attnout[(size_t)MROWS * D];
__device__ float g_tmp    [(size_t)MROWS * D];
__device__ float g_x      [(size_t)MROWS * D];
__device__ float g_hid    [(size_t)MROWS * DFF];
__device__ float g_attw   [(size_t)MROWS * NH * NP];
__device__ float g_offs   [(size_t)MROWS * NH * NP * 2];

// =====================================================================
// Top-4 over 7x7 window of (w*mask + b), pad=0, stable ties (lower idx).
// Then softmax over the 4 values, divided by 4 (NL-broadcast softmax16).
// =====================================================================
__global__ void topk_kernel(const float* __restrict__ m0, const float* __restrict__ m1,
                            const float* __restrict__ m2, const float* __restrict__ m3,
                            const float* __restrict__ pmw, const float* __restrict__ pmb)
{
    int t = blockIdx.x * blockDim.x + threadIdx.x;
    if (t >= MROWS * NH) return;
    int h = t % NH;
    int r = t / NH;          // b*LEN + q
    int q = r % LEN;
    int b = r / LEN;

    int l, Wl, s0;
    const float* mk;
    if (q < 8464)        { l = 0; Wl = 92; s0 = 0;     mk = m0; }
    else if (q < 10580)  { l = 1; Wl = 46; s0 = 8464;  mk = m1; }
    else if (q < 11109)  { l = 2; Wl = 23; s0 = 10580; mk = m2; }
    else                 { l = 3; Wl = 12; s0 = 11109; mk = m3; }
    int Hl = Wl;
    int pos = q - s0;
    int y = pos / Wl, x = pos % Wl;

    float w  = pmw[l * NH + h];
    float bb = pmb[l * NH + h];
    const float* mb = mk + (size_t)b * Hl * Wl;

    float tv[4] = {-1e30f, -1e30f, -1e30f, -1e30f};
    int   ti[4] = {0, 0, 0, 0};

    for (int i = 0; i < 7; i++) {
        int yy = y + i - 3;
        for (int j = 0; j < 7; j++) {
            int xx = x + j - 3;
            float val = 0.0f;
            if (yy >= 0 && yy < Hl && xx >= 0 && xx < Wl)
                val = fmaf(mb[yy * Wl + xx], w, bb);
            if (val > tv[3]) {              // strict >: stable (earlier idx stays)
                int k = i * 7 + j;
                tv[3] = val; ti[3] = k;
                if (tv[3] > tv[2]) { float fv = tv[2]; tv[2] = tv[3]; tv[3] = fv; int iv = ti[2]; ti[2] = ti[3]; ti[3] = iv; }
                if (tv[2] > tv[1]) { float fv = tv[1]; tv[1] = tv[2]; tv[2] = fv; int iv = ti[1]; ti[1] = ti[2]; ti[2] = iv; }
                if (tv[1] > tv[0]) { float fv = tv[0]; tv[0] = tv[1]; tv[1] = fv; int iv = ti[0]; ti[0] = ti[1]; ti[1] = iv; }
            }
        }
    }

    // softmax over 4 values / 4 (== softmax over NL*NP broadcast)
    float mx = tv[0];
    float e0 = expf(tv[0] - mx), e1 = expf(tv[1] - mx),
          e2 = expf(tv[2] - mx), e3 = expf(tv[3] - mx);
    float inv = 1.0f / (4.0f * (e0 + e1 + e2 + e3));

    int base = (r * NH + h) * NP;
    float ee[4] = {e0, e1, e2, e3};
#pragma unroll
    for (int p = 0; p < 4; p++) {
        g_attw[base + p] = ee[p] * inv;
        g_offs[(size_t)(base + p) * 2 + 0] = (float)(ti[p] % 7 - 3);  // x off
        g_offs[(size_t)(base + p) * 2 + 1] = (float)(ti[p] / 7 - 3);  // y off
    }
}

// =====================================================================
// SGEMM 128x128x8, 256 threads, 8x8 per thread. C = A@B + bias (opt relu)
// A: MxK row-major, B: KxN row-major, N multiple of 128, K multiple of 8.
// =====================================================================
template<int RELU>
__global__ __launch_bounds__(256, 2)
void sgemm_kernel(const float* __restrict__ A, const float* __restrict__ B,
                  const float* __restrict__ bias, float* __restrict__ C,
                  int M, int N, int K)
{
    __shared__ float As[8][128];
    __shared__ float Bs[8][128];

    int tid = threadIdx.x;
    int bx = blockIdx.x, by = blockIdx.y;

    int rowA  = by * 128 + (tid >> 1);
    int colA4 = (tid & 1) * 4;
    int rowB  = tid >> 5;
    int colB4 = (tid & 31) * 4;

    int tx = tid & 15, ty = tid >> 4;

    float acc[8][8];
#pragma unroll
    for (int i = 0; i < 8; i++)
#pragma unroll
        for (int j = 0; j < 8; j++) acc[i][j] = 0.0f;

    for (int k0 = 0; k0 < K; k0 += 8) {
        float4 a4 = make_float4(0.f, 0.f, 0.f, 0.f);
        if (rowA < M)
            a4 = *(const float4*)(A + (size_t)rowA * K + k0 + colA4);
        As[colA4 + 0][tid >> 1] = a4.x;
        As[colA4 + 1][tid >> 1] = a4.y;
        As[colA4 + 2][tid >> 1] = a4.z;
        As[colA4 + 3][tid >> 1] = a4.w;

        float4 b4 = *(const float4*)(B + (size_t)(k0 + rowB) * N + bx * 128 + colB4);
        *(float4*)&Bs[rowB][colB4] = b4;

        __syncthreads();
#pragma unroll
        for (int kk = 0; kk < 8; kk++) {
            float a[8], bf[8];
#pragma unroll
            for (int i = 0; i < 8; i++) a[i]  = As[kk][ty * 8 + i];
#pragma unroll
            for (int j = 0; j < 8; j++) bf[j] = Bs[kk][tx * 8 + j];
#pragma unroll
            for (int i = 0; i < 8; i++)
#pragma unroll
                for (int j = 0; j < 8; j++)
                    acc[i][j] = fmaf(a[i], bf[j], acc[i][j]);
        }
        __syncthreads();
    }

    int crow0 = by * 128 + ty * 8;
    int ccol0 = bx * 128 + tx * 8;
#pragma unroll
    for (int i = 0; i < 8; i++) {
        int row = crow0 + i;
        if (row < M) {
#pragma unroll
            for (int j = 0; j < 8; j++) {
                float v = acc[i][j] + bias[ccol0 + j];
                if (RELU) v = fmaxf(v, 0.0f);
                C[(size_t)row * N + ccol0 + j] = v;
            }
        }
    }
}

// =====================================================================
// Deformable sampling: one block = one (b,q); one warp = one head;
// lane = channel (DH=32). Bilinear over 4 levels x 4 points.
// =====================================================================
__global__ void sample_kernel(const float* __restrict__ ref)
{
    int r = blockIdx.x;                 // b*LEN + q
    int h = threadIdx.x >> 5;
    int lane = threadIdx.x & 31;
    int b = r / LEN;

    const int   Hs[4] = {92, 46, 23, 12};
    const int   S0[4] = {0, 8464, 10580, 11109};

    int base = (r * NH + h) * NP;
    float acc = 0.0f;

#pragma unroll
    for (int l = 0; l < 4; l++) {
        int   Wi  = Hs[l];
        float Wf  = (float)Wi;
        float rx = ref[(size_t)(r * NL + l) * 2 + 0];
        float ry = ref[(size_t)(r * NL + l) * 2 + 1];
        const float* vb = g_value + ((size_t)b * LEN + S0[l]) * D + h * DH + lane;

#pragma unroll
        for (int p = 0; p < NP; p++) {
            float wgt = g_attw[base + p];
            float ox  = g_offs[(size_t)(base + p) * 2 + 0];
            float oy  = g_offs[(size_t)(base + p) * 2 + 1];
            float locx = rx + ox / Wf;
            float locy = ry + oy / Wf;     // square levels: H == W
            float xf = locx * Wf - 0.5f;
            float yf = locy * Wf - 0.5f;
            float x0f = floorf(xf), y0f = floorf(yf);
            float tx = xf - x0f, ty = yf - y0f;
            int x0 = (int)x0f, y0 = (int)y0f;
            int x1 = x0 + 1,  y1 = y0 + 1;

            float w00 = (1.0f - tx) * (1.0f - ty);
            float w01 = tx * (1.0f - ty);
            float w10 = (1.0f - tx) * ty;
            float w11 = tx * ty;

            bool vx0 = (x0 >= 0) & (x0 < Wi);
            bool vx1 = (x1 >= 0) & (x1 < Wi);
            bool vy0 = (y0 >= 0) & (y0 < Wi);
            bool vy1 = (y1 >= 0) & (y1 < Wi);

            float s = 0.0f;
            if (vy0 & vx0) s = fmaf(w00, vb[(size_t)(y0 * Wi + x0) * D], s);
            if (vy0 & vx1) s = fmaf(w01, vb[(size_t)(y0 * Wi + x1) * D], s);
            if (vy1 & vx0) s = fmaf(w10, vb[(size_t)(y1 * Wi + x0) * D], s);
            if (vy1 & vx1) s = fmaf(w11, vb[(size_t)(y1 * Wi + x1) * D], s);
            acc = fmaf(wgt, s, acc);
        }
    }
    g_attnout[(size_t)r * D + h * DH + lane] = acc;
}

// =====================================================================
// out = LayerNorm(a + res) * g + b, row width 256, one block per row
// =====================================================================
__global__ void add_ln_kernel(const float* __restrict__ a, const float* __restrict__ res,
                              const float* __restrict__ gg, const float* __restrict__ bb,
                              float* __restrict__ out)
{
    int row = blockIdx.x;
    int t = threadIdx.x;
    float v = a[(size_t)row * D + t] + res[(size_t)row * D + t];

    __shared__ float s1[8], s2[8];
    float s = v, u = v * v;
#pragma unroll
    for (int o = 16; o; o >>= 1) {
        s += __shfl_xor_sync(0xffffffffu, s, o);
        u += __shfl_xor_sync(0xffffffffu, u, o);
    }
    if ((t & 31) == 0) { s1[t >> 5] = s; s2[t >> 5] = u; }
    __syncthreads();
    float sum = 0.f, sq = 0.f;
#pragma unroll
    for (int i = 0; i < 8; i++) { sum += s1[i]; sq += s2[i]; }
    float mean = sum * (1.0f / D);
    float var  = sq * (1.0f / D) - mean * mean;
    float rs = rsqrtf(var + 1e-5f);
    out[(size_t)row * D + t] = (v - mean) * rs * gg[t] + bb[t];
}

// =====================================================================
extern "C" void kernel_launch(void* const* d_in, const int* in_sizes, int n_in,
                              void* d_out, int out_size)
{
    const float* src  = (const float*)d_in[0];
    const float* ref  = (const float*)d_in[2];
    const float* m0   = (const float*)d_in[4];
    const float* m1   = (const float*)d_in[5];
    const float* m2   = (const float*)d_in[6];
    const float* m3   = (const float*)d_in[7];
    const float* pmw  = (const float*)d_in[10];
    const float* pmb  = (const float*)d_in[11];
    const float* Wv   = (const float*)d_in[12];
    const float* bv   = (const float*)d_in[13];
    const float* Wo   = (const float*)d_in[14];
    const float* bo   = (const float*)d_in[15];
    const float* ln1g = (const float*)d_in[16];
    const float* ln1b = (const float*)d_in[17];
    const float* W1   = (const float*)d_in[18];
    const float* b1   = (const float*)d_in[19];
    const float* W2   = (const float*)d_in[20];
    const float* b2   = (const float*)d_in[21];
    const float* ln2g = (const float*)d_in[22];
    const float* ln2b = (const float*)d_in[23];
    float* out = (float*)d_out;

    float *pv, *pao, *ptmp, *px, *ph;
    cudaGetSymbolAddress((void**)&pv,  g_value);
    cudaGetSymbolAddress((void**)&pao, g_attnout);
    cudaGetSymbolAddress((void**)&ptmp,g_tmp);
    cudaGetSymbolAddress((void**)&px,  g_x);
    cudaGetSymbolAddress((void**)&ph,  g_hid);

    const int MB = (MROWS + 127) / 128;   // 176

    // 1. top-k offsets + attention weights
    topk_kernel<<<(MROWS * NH + 255) / 256, 256>>>(m0, m1, m2, m3, pmw, pmb);

    // 2. value = src @ Wv + bv
    sgemm_kernel<0><<<dim3(2, MB), 256>>>(src, Wv, bv, pv, MROWS, 256, 256);

    // 3. deformable bilinear sampling -> attnout (pre-Wo)
    sample_kernel<<<MROWS, 256>>>(ref);

    // 4. attn_out = attnout @ Wo + bo
    sgemm_kernel<0><<<dim3(2, MB), 256>>>(pao, Wo, bo, ptmp, MROWS, 256, 256);

    // 5. x = LN(src + attn_out)
    add_ln_kernel<<<MROWS, 256>>>(ptmp, src, ln1g, ln1b, px);

    // 6. hid = relu(x @ W1 + b1)
    sgemm_kernel<1><<<dim3(8, MB), 256>>>(px, W1, b1, ph, MROWS, 1024, 256);

    // 7. y = hid @ W2 + b2
    sgemm_kernel<0><<<dim3(2, MB), 256>>>(ph, W2, b2, ptmp, MROWS, 256, 1024);

    // 8. out = LN(x + y)
    add_ln_kernel<<<MROWS, 256>>>(ptmp, px, ln2g, ln2b, out);
}

// round 3
// speedup vs baseline: 2.2338x; 2.2338x over previous
#include <cuda_runtime.h>
#include <cstdint>
#include <math.h>

#define BS   2
#define LEN  11253
#define MROWS (BS*LEN)   // 22506
#define D    256
#define NH   8
#define NP   4
#define NL   4
#define DH   32
#define DFF  1024

// ---- scratch (device globals; no allocation allowed) ----
__device__ float g_value  [(size_t)MROWS * D];
__device__ float g_attnout[(size_t)MROWS * D];
__device__ float g_tmp    [(size_t)MROWS * D];
__device__ float g_x      [(size_t)MROWS * D];
__device__ float g_hid    [(size_t)MROWS * DFF];
__device__ float g_attw   [(size_t)MROWS * NH * NP];
__device__ float g_offs   [(size_t)MROWS * NH * NP * 2];
__device__ float g_WvT    [D * D];
__device__ float g_WoT    [D * D];
__device__ float g_W1T    [DFF * D];
__device__ float g_W2T    [D * DFF];

// =====================================================================
// helpers
// =====================================================================
__device__ __forceinline__ uint32_t f2tf32(float x) {
    uint32_t r;
    asm("cvt.rna.tf32.f32 %0, %1;" : "=r"(r) : "f"(x));
    return r;
}
__device__ __forceinline__ void mma_tf32(float* d, const uint32_t* a, const uint32_t* b) {
    asm volatile(
        "mma.sync.aligned.m16n8k8.row.col.f32.tf32.tf32.f32 "
        "{%0,%1,%2,%3}, {%4,%5,%6,%7}, {%8,%9}, {%0,%1,%2,%3};"
        : "+f"(d[0]), "+f"(d[1]), "+f"(d[2]), "+f"(d[3])
        : "r"(a[0]), "r"(a[1]), "r"(a[2]), "r"(a[3]), "r"(b[0]), "r"(b[1]));
}

// =====================================================================
// TF32 tensor-core GEMM: C[M,N] = A[M,K] @ BT[N,K]^T + bias (opt relu)
// 128x128 CTA tile, BK=32, 3-stage cp.async, 8 warps (4x2), 32x64/warp.
// Smem layout: As[r][k] stride 36 floats; Bs[n][k] stride 36 floats.
// Fragment LDS are bank-conflict-free (bank = 4*group + quad, bijective).
// BT must be tf32-pre-rounded (done in transpose); A frags cvt at load.
// =====================================================================
#define SSTRIDE     36
#define TILE_F      (128*SSTRIDE)         // floats per operand tile
#define STAGE_B     (2*TILE_F*4)          // bytes per stage (36864)
#define GEMM_SMEM   (3*STAGE_B)           // 110592

template<int RELU>
__global__ void __launch_bounds__(256)
gemm_tc(const float* __restrict__ A, const float* __restrict__ BT,
        const float* __restrict__ bias, float* __restrict__ C,
        int M, int N, int K)
{
    extern __shared__ float smem[];
    int tid = threadIdx.x, wid = tid >> 5, lane = tid & 31;
    int g = lane >> 2, qc = lane & 3;
    int row0 = blockIdx.y * 128, col0 = blockIdx.x * 128;
    int wm = (wid & 3) * 32, wn = (wid >> 2) * 64;

    const int NC = K >> 5;

    auto load_chunk = [&](int c, int s) {
        float* As = smem + s * (2 * TILE_F);
        float* Bs = As + TILE_F;
        int k0 = c * 32;
        const float* Ab = A + (size_t)row0 * K + k0;
        const float* Bb = BT + (size_t)col0 * K + k0;
        uint32_t a_st, b_st;
        asm("{ .reg .u64 t; cvta.to.shared.u64 t, %1; cvt.u32.u64 %0, t; }" : "=r"(a_st) : "l"(As));
        asm("{ .reg .u64 t; cvta.to.shared.u64 t, %1; cvt.u32.u64 %0, t; }" : "=r"(b_st) : "l"(Bs));
#pragma unroll
        for (int i = 0; i < 4; i++) {
            int f4 = tid + i * 256;        // 1024 float4 per tile
            int r = f4 >> 3, c4 = f4 & 7;
            uint32_t off = (uint32_t)(r * SSTRIDE + c4 * 4) * 4;
            uint32_t nbytes = (row0 + r < M) ? 16u : 0u;
            asm volatile("cp.async.cg.shared.global [%0], [%1], 16, %2;"
                :: "r"(a_st + off), "l"(Ab + (size_t)r * K + c4 * 4), "r"(nbytes));
            asm volatile("cp.async.cg.shared.global [%0], [%1], 16;"
                :: "r"(b_st + off), "l"(Bb + (size_t)r * K + c4 * 4));
        }
    };

    float acc[2][8][4];
#pragma unroll
    for (int mt = 0; mt < 2; mt++)
#pragma unroll
        for (int nt = 0; nt < 8; nt++)
#pragma unroll
            for (int i = 0; i < 4; i++) acc[mt][nt][i] = 0.0f;

    load_chunk(0, 0);
    asm volatile("cp.async.commit_group;");
    load_chunk(1, 1);
    asm volatile("cp.async.commit_group;");

    for (int c = 0; c < NC; c++) {
        if (c + 2 < NC) load_chunk(c + 2, (c + 2) % 3);
        asm volatile("cp.async.commit_group;");
        asm volatile("cp.async.wait_group 2;");
        __syncthreads();

        const float* As = smem + (c % 3) * (2 * TILE_F);
        const float* Bs = As + TILE_F;
#pragma unroll
        for (int ks = 0; ks < 4; ks++) {
            int k0 = ks * 8 + qc;
            uint32_t af[2][4];
#pragma unroll
            for (int mt = 0; mt < 2; mt++) {
                int r = wm + mt * 16 + g;
                af[mt][0] = f2tf32(As[r * SSTRIDE + k0]);
                af[mt][1] = f2tf32(As[(r + 8) * SSTRIDE + k0]);
                af[mt][2] = f2tf32(As[r * SSTRIDE + k0 + 4]);
                af[mt][3] = f2tf32(As[(r + 8) * SSTRIDE + k0 + 4]);
            }
            uint32_t bf[8][2];
#pragma unroll
            for (int nt = 0; nt < 8; nt++) {
                int n = wn + nt * 8 + g;
                bf[nt][0] = __float_as_uint(Bs[n * SSTRIDE + k0]);
                bf[nt][1] = __float_as_uint(Bs[n * SSTRIDE + k0 + 4]);
            }
#pragma unroll
            for (int mt = 0; mt < 2; mt++)
#pragma unroll
                for (int nt = 0; nt < 8; nt++)
                    mma_tf32(acc[mt][nt], af[mt], bf[nt]);
        }
        __syncthreads();
    }

    // epilogue
#pragma unroll
    for (int mt = 0; mt < 2; mt++) {
        int r0 = row0 + wm + mt * 16 + g;
#pragma unroll
        for (int nt = 0; nt < 8; nt++) {
            int col = col0 + wn + nt * 8 + 2 * qc;
            float b0 = bias[col], b1 = bias[col + 1];
            if (r0 < M) {
                float2 v = make_float2(acc[mt][nt][0] + b0, acc[mt][nt][1] + b1);
                if (RELU) { v.x = fmaxf(v.x, 0.f); v.y = fmaxf(v.y, 0.f); }
                *(float2*)(C + (size_t)r0 * N + col) = v;
            }
            if (r0 + 8 < M) {
                float2 v = make_float2(acc[mt][nt][2] + b0, acc[mt][nt][3] + b1);
                if (RELU) { v.x = fmaxf(v.x, 0.f); v.y = fmaxf(v.y, 0.f); }
                *(float2*)(C + (size_t)(r0 + 8) * N + col) = v;
            }
        }
    }
}

// =====================================================================
// Tiled transpose + tf32 rounding: dst[C,R] = tf32(src[R,C])^T
// =====================================================================
__global__ void transpose_kernel(const float* __restrict__ src, float* __restrict__ dst,
                                 int R, int C)
{
    __shared__ float t[32][33];
    int bx = blockIdx.x * 32, by = blockIdx.y * 32;
#pragma unroll
    for (int i = 0; i < 32; i += 8) {
        int r = by + threadIdx.y + i, c = bx + threadIdx.x;
        if (r < R && c < C)
            t[threadIdx.y + i][threadIdx.x] = __uint_as_float(f2tf32(src[(size_t)r * C + c]));
    }
    __syncthreads();
#pragma unroll
    for (int i = 0; i < 32; i += 8) {
        int r = bx + threadIdx.y + i, c = by + threadIdx.x;
        if (r < C && c < R) dst[(size_t)r * R + c] = t[threadIdx.x][threadIdx.y + i];
    }
}

// =====================================================================
// Top-4 over 7x7 window of (w*mask + b), pad=0, stable ties (lower idx).
// =====================================================================
__global__ void topk_kernel(const float* __restrict__ m0, const float* __restrict__ m1,
                            const float* __restrict__ m2, const float* __restrict__ m3,
                            const float* __restrict__ pmw, const float* __restrict__ pmb)
{
    int t = blockIdx.x * blockDim.x + threadIdx.x;
    if (t >= MROWS * NH) return;
    int h = t % NH;
    int r = t / NH;
    int q = r % LEN;
    int b = r / LEN;

    int l, Wl, s0;
    const float* mk;
    if (q < 8464)        { l = 0; Wl = 92; s0 = 0;     mk = m0; }
    else if (q < 10580)  { l = 1; Wl = 46; s0 = 8464;  mk = m1; }
    else if (q < 11109)  { l = 2; Wl = 23; s0 = 10580; mk = m2; }
    else                 { l = 3; Wl = 12; s0 = 11109; mk = m3; }
    int Hl = Wl;
    int pos = q - s0;
    int y = pos / Wl, x = pos % Wl;

    float w  = pmw[l * NH + h];
    float bb = pmb[l * NH + h];
    const float* mb = mk + (size_t)b * Hl * Wl;

    float tv[4] = {-1e30f, -1e30f, -1e30f, -1e30f};
    int   ti[4] = {0, 0, 0, 0};

    for (int i = 0; i < 7; i++) {
        int yy = y + i - 3;
        for (int j = 0; j < 7; j++) {
            int xx = x + j - 3;
            float val = 0.0f;
            if (yy >= 0 && yy < Hl && xx >= 0 && xx < Wl)
                val = fmaf(mb[yy * Wl + xx], w, bb);
            if (val > tv[3]) {
                int k = i * 7 + j;
                tv[3] = val; ti[3] = k;
                if (tv[3] > tv[2]) { float fv = tv[2]; tv[2] = tv[3]; tv[3] = fv; int iv = ti[2]; ti[2] = ti[3]; ti[3] = iv; }
                if (tv[2] > tv[1]) { float fv = tv[1]; tv[1] = tv[2]; tv[2] = fv; int iv = ti[1]; ti[1] = ti[2]; ti[2] = iv; }
                if (tv[1] > tv[0]) { float fv = tv[0]; tv[0] = tv[1]; tv[1] = fv; int iv = ti[0]; ti[0] = ti[1]; ti[1] = iv; }
            }
        }
    }

    float mx = tv[0];
    float e0 = expf(tv[0] - mx), e1 = expf(tv[1] - mx),
          e2 = expf(tv[2] - mx), e3 = expf(tv[3] - mx);
    float inv = 1.0f / (4.0f * (e0 + e1 + e2 + e3));

    int base = (r * NH + h) * NP;
    float ee[4] = {e0, e1, e2, e3};
#pragma unroll
    for (int p = 0; p < 4; p++) {
        g_attw[base + p] = ee[p] * inv;
        g_offs[(size_t)(base + p) * 2 + 0] = (float)(ti[p] % 7 - 3);
        g_offs[(size_t)(base + p) * 2 + 1] = (float)(ti[p] / 7 - 3);
    }
}

// =====================================================================
// Deformable sampling
// =====================================================================
__global__ void sample_kernel(const float* __restrict__ ref)
{
    int r = blockIdx.x;
    int h = threadIdx.x >> 5;
    int lane = threadIdx.x & 31;
    int b = r / LEN;

    const int Hs[4] = {92, 46, 23, 12};
    const int S0[4] = {0, 8464, 10580, 11109};

    int base = (r * NH + h) * NP;
    float acc = 0.0f;

#pragma unroll
    for (int l = 0; l < 4; l++) {
        int   Wi = Hs[l];
        float Wf = (float)Wi;
        float rx = ref[(size_t)(r * NL + l) * 2 + 0];
        float ry = ref[(size_t)(r * NL + l) * 2 + 1];
        const float* vb = g_value + ((size_t)b * LEN + S0[l]) * D + h * DH + lane;

#pragma unroll
        for (int p = 0; p < NP; p++) {
            float wgt = g_attw[base + p];
            float ox  = g_offs[(size_t)(base + p) * 2 + 0];
            float oy  = g_offs[(size_t)(base + p) * 2 + 1];
            float locx = rx + ox / Wf;
            float locy = ry + oy / Wf;
            float xf = locx * Wf - 0.5f;
            float yf = locy * Wf - 0.5f;
            float x0f = floorf(xf), y0f = floorf(yf);
            float tx = xf - x0f, ty = yf - y0f;
            int x0 = (int)x0f, y0 = (int)y0f;
            int x1 = x0 + 1,  y1 = y0 + 1;

            float w00 = (1.0f - tx) * (1.0f - ty);
            float w01 = tx * (1.0f - ty);
            float w10 = (1.0f - tx) * ty;
            float w11 = tx * ty;

            bool vx0 = (x0 >= 0) & (x0 < Wi);
            bool vx1 = (x1 >= 0) & (x1 < Wi);
            bool vy0 = (y0 >= 0) & (y0 < Wi);
            bool vy1 = (y1 >= 0) & (y1 < Wi);

            float s = 0.0f;
            if (vy0 & vx0) s = fmaf(w00, vb[(size_t)(y0 * Wi + x0) * D], s);
            if (vy0 & vx1) s = fmaf(w01, vb[(size_t)(y0 * Wi + x1) * D], s);
            if (vy1 & vx0) s = fmaf(w10, vb[(size_t)(y1 * Wi + x0) * D], s);
            if (vy1 & vx1) s = fmaf(w11, vb[(size_t)(y1 * Wi + x1) * D], s);
            acc = fmaf(wgt, s, acc);
        }
    }
    g_attnout[(size_t)r * D + h * DH + lane] = acc;
}

// =====================================================================
// out = LayerNorm(a + res) * g + b
// =====================================================================
__global__ void add_ln_kernel(const float* __restrict__ a, const float* __restrict__ res,
                              const float* __restrict__ gg, const float* __restrict__ bb,
                              float* __restrict__ out)
{
    int row = blockIdx.x;
    int t = threadIdx.x;
    float v = a[(size_t)row * D + t] + res[(size_t)row * D + t];

    __shared__ float s1[8], s2[8];
    float s = v, u = v * v;
#pragma unroll
    for (int o = 16; o; o >>= 1) {
        s += __shfl_xor_sync(0xffffffffu, s, o);
        u += __shfl_xor_sync(0xffffffffu, u, o);
    }
    if ((t & 31) == 0) { s1[t >> 5] = s; s2[t >> 5] = u; }
    __syncthreads();
    float sum = 0.f, sq = 0.f;
#pragma unroll
    for (int i = 0; i < 8; i++) { sum += s1[i]; sq += s2[i]; }
    float mean = sum * (1.0f / D);
    float var  = sq * (1.0f / D) - mean * mean;
    float rs = rsqrtf(var + 1e-5f);
    out[(size_t)row * D + t] = (v - mean) * rs * gg[t] + bb[t];
}

// =====================================================================
extern "C" void kernel_launch(void* const* d_in, const int* in_sizes, int n_in,
                              void* d_out, int out_size)
{
    const float* src  = (const float*)d_in[0];
    const float* ref  = (const float*)d_in[2];
    const float* m0   = (const float*)d_in[4];
    const float* m1   = (const float*)d_in[5];
    const float* m2   = (const float*)d_in[6];
    const float* m3   = (const float*)d_in[7];
    const float* pmw  = (const float*)d_in[10];
    const float* pmb  = (const float*)d_in[11];
    const float* Wv   = (const float*)d_in[12];
    const float* bv   = (const float*)d_in[13];
    const float* Wo   = (const float*)d_in[14];
    const float* bo   = (const float*)d_in[15];
    const float* ln1g = (const float*)d_in[16];
    const float* ln1b = (const float*)d_in[17];
    const float* W1   = (const float*)d_in[18];
    const float* b1   = (const float*)d_in[19];
    const float* W2   = (const float*)d_in[20];
    const float* b2   = (const float*)d_in[21];
    const float* ln2g = (const float*)d_in[22];
    const float* ln2b = (const float*)d_in[23];
    float* out = (float*)d_out;

    float *pv, *pao, *ptmp, *px, *ph, *pWvT, *pWoT, *pW1T, *pW2T;
    cudaGetSymbolAddress((void**)&pv,   g_value);
    cudaGetSymbolAddress((void**)&pao,  g_attnout);
    cudaGetSymbolAddress((void**)&ptmp, g_tmp);
    cudaGetSymbolAddress((void**)&px,   g_x);
    cudaGetSymbolAddress((void**)&ph,   g_hid);
    cudaGetSymbolAddress((void**)&pWvT, g_WvT);
    cudaGetSymbolAddress((void**)&pWoT, g_WoT);
    cudaGetSymbolAddress((void**)&pW1T, g_W1T);
    cudaGetSymbolAddress((void**)&pW2T, g_W2T);

    cudaFuncSetAttribute(gemm_tc<0>, cudaFuncAttributeMaxDynamicSharedMemorySize, GEMM_SMEM);
    cudaFuncSetAttribute(gemm_tc<1>, cudaFuncAttributeMaxDynamicSharedMemorySize, GEMM_SMEM);

    const int MB = (MROWS + 127) / 128;   // 176
    dim3 tb(32, 8);

    // 0. weight transposes + tf32 rounding (B^T, K-major)
    transpose_kernel<<<dim3(8, 8),   tb>>>(Wv, pWvT, 256, 256);
    transpose_kernel<<<dim3(8, 8),   tb>>>(Wo, pWoT, 256, 256);
    transpose_kernel<<<dim3(32, 8),  tb>>>(W1, pW1T, 256, 1024);
    transpose_kernel<<<dim3(8, 32),  tb>>>(W2, pW2T, 1024, 256);

    // 1. top-k offsets + attention weights
    topk_kernel<<<(MROWS * NH + 255) / 256, 256>>>(m0, m1, m2, m3, pmw, pmb);

    // 2. value = src @ Wv + bv
    gemm_tc<0><<<dim3(2, MB), 256, GEMM_SMEM>>>(src, pWvT, bv, pv, MROWS, 256, 256);

    // 3. deformable bilinear sampling -> attnout (pre-Wo)
    sample_kernel<<<MROWS, 256>>>(ref);

    // 4. attn_out = attnout @ Wo + bo
    gemm_tc<0><<<dim3(2, MB), 256, GEMM_SMEM>>>(pao, pWoT, bo, ptmp, MROWS, 256, 256);

    // 5. x = LN(src + attn_out)
    add_ln_kernel<<<MROWS, 256>>>(ptmp, src, ln1g, ln1b, px);

    // 6. hid = relu(x @ W1 + b1)
    gemm_tc<1><<<dim3(8, MB), 256, GEMM_SMEM>>>(px, pW1T, b1, ph, MROWS, 1024, 256);

    // 7. y = hid @ W2 + b2
    gemm_tc<0><<<dim3(2, MB), 256, GEMM_SMEM>>>(ph, pW2T, b2, ptmp, MROWS, 256, 1024);

    // 8. out = LN(x + y)
    add_ln_kernel<<<MROWS, 256>>>(ptmp, px, ln2g, ln2b, out);
}

// round 4
// speedup vs baseline: 2.2912x; 1.0257x over previous
#include <cuda_runtime.h>
#include <cstdint>
#include <math.h>

#define BS   2
#define LEN  11253
#define MROWS (BS*LEN)   // 22506
#define D    256
#define NH   8
#define NP   4
#define NL   4
#define DH   32
#define DFF  1024

// ---- scratch (device globals; no allocation allowed) ----
__device__ float g_value  [(size_t)MROWS * D];
__device__ float g_attnout[(size_t)MROWS * D];
__device__ float g_tmp    [(size_t)MROWS * D];
__device__ float g_x      [(size_t)MROWS * D];
__device__ float g_hid    [(size_t)MROWS * DFF];
__device__ float g_attw   [(size_t)MROWS * NH * NP];
__device__ float g_offs   [(size_t)MROWS * NH * NP * 2];
__device__ float g_WvT    [D * D];
__device__ float g_WoT    [D * D];
__device__ float g_W1T    [DFF * D];
__device__ float g_W2T    [D * DFF];

// =====================================================================
// helpers
// =====================================================================
__device__ __forceinline__ uint32_t f2tf32(float x) {
    uint32_t r;
    asm("cvt.rna.tf32.f32 %0, %1;" : "=r"(r) : "f"(x));
    return r;
}
__device__ __forceinline__ void mma_tf32(float* d, const uint32_t* a, const uint32_t* b) {
    asm volatile(
        "mma.sync.aligned.m16n8k8.row.col.f32.tf32.tf32.f32 "
        "{%0,%1,%2,%3}, {%4,%5,%6,%7}, {%8,%9}, {%0,%1,%2,%3};"
        : "+f"(d[0]), "+f"(d[1]), "+f"(d[2]), "+f"(d[3])
        : "r"(a[0]), "r"(a[1]), "r"(a[2]), "r"(a[3]), "r"(b[0]), "r"(b[1]));
}

// =====================================================================
// TF32 tensor-core GEMM: C[M,N] = A[M,K] @ BT[N,K]^T + bias (opt relu)
// 128x128 CTA tile, BK=32, 3-stage cp.async, 4 warps (2x2), 64x64/warp.
// Smem: As[r][k], Bs[n][k], stride 36 floats (fragment LDS conflict-free:
// bank = 4*group + quad, bijective over warp).
// One __syncthreads per chunk. BT tf32-pre-rounded; A cvt at fragment load.
// =====================================================================
#define SSTRIDE     36
#define TILE_F      (128*SSTRIDE)
#define STAGE_F     (2*TILE_F)
#define GEMM_SMEM   (3*STAGE_F*4)         // 110592 B

template<int RELU>
__global__ void __launch_bounds__(128, 2)
gemm_tc(const float* __restrict__ A, const float* __restrict__ BT,
        const float* __restrict__ bias, float* __restrict__ C,
        int M, int N, int K)
{
    extern __shared__ float smem[];
    int tid = threadIdx.x, wid = tid >> 5, lane = tid & 31;
    int g = lane >> 2, qc = lane & 3;
    int row0 = blockIdx.y * 128, col0 = blockIdx.x * 128;
    int wm = (wid & 1) * 64, wn = (wid >> 1) * 64;

    const int NC = K >> 5;

    auto load_chunk = [&](int c) {
        if (c >= NC) { asm volatile("cp.async.commit_group;"); return; }
        float* As = smem + (c % 3) * STAGE_F;
        float* Bs = As + TILE_F;
        int k0 = c * 32;
        const float* Ab = A + (size_t)row0 * K + k0;
        const float* Bb = BT + (size_t)col0 * K + k0;
        uint32_t a_st, b_st;
        asm("{ .reg .u64 t; cvta.to.shared.u64 t, %1; cvt.u32.u64 %0, t; }" : "=r"(a_st) : "l"(As));
        asm("{ .reg .u64 t; cvta.to.shared.u64 t, %1; cvt.u32.u64 %0, t; }" : "=r"(b_st) : "l"(Bs));
#pragma unroll
        for (int i = 0; i < 8; i++) {
            int f4 = tid + i * 128;            // 1024 float4 per tile
            int r = f4 >> 3, c4 = f4 & 7;
            uint32_t off = (uint32_t)(r * SSTRIDE + c4 * 4) * 4;
            uint32_t nbytes = (row0 + r < M) ? 16u : 0u;
            asm volatile("cp.async.cg.shared.global [%0], [%1], 16, %2;"
                :: "r"(a_st + off), "l"(Ab + (size_t)r * K + c4 * 4), "r"(nbytes));
            asm volatile("cp.async.cg.shared.global [%0], [%1], 16;"
                :: "r"(b_st + off), "l"(Bb + (size_t)r * K + c4 * 4));
        }
        asm volatile("cp.async.commit_group;");
    };

    float acc[4][8][4];
#pragma unroll
    for (int mt = 0; mt < 4; mt++)
#pragma unroll
        for (int nt = 0; nt < 8; nt++)
#pragma unroll
            for (int i = 0; i < 4; i++) acc[mt][nt][i] = 0.0f;

    load_chunk(0);
    load_chunk(1);

    for (int c = 0; c < NC; c++) {
        asm volatile("cp.async.wait_group 1;");
        __syncthreads();
        load_chunk(c + 2);   // target stage read 2 barriers ago -> safe

        const float* As = smem + (c % 3) * STAGE_F;
        const float* Bs = As + TILE_F;
#pragma unroll
        for (int ks = 0; ks < 4; ks++) {
            int k0 = ks * 8 + qc;
            uint32_t af[4][4];
#pragma unroll
            for (int mt = 0; mt < 4; mt++) {
                int r = wm + mt * 16 + g;
                af[mt][0] = f2tf32(As[r * SSTRIDE + k0]);
                af[mt][1] = f2tf32(As[(r + 8) * SSTRIDE + k0]);
                af[mt][2] = f2tf32(As[r * SSTRIDE + k0 + 4]);
                af[mt][3] = f2tf32(As[(r + 8) * SSTRIDE + k0 + 4]);
            }
            uint32_t bf[8][2];
#pragma unroll
            for (int nt = 0; nt < 8; nt++) {
                int n = wn + nt * 8 + g;
                bf[nt][0] = __float_as_uint(Bs[n * SSTRIDE + k0]);
                bf[nt][1] = __float_as_uint(Bs[n * SSTRIDE + k0 + 4]);
            }
#pragma unroll
            for (int mt = 0; mt < 4; mt++)
#pragma unroll
                for (int nt = 0; nt < 8; nt++)
                    mma_tf32(acc[mt][nt], af[mt], bf[nt]);
        }
    }

    // epilogue
#pragma unroll
    for (int mt = 0; mt < 4; mt++) {
        int r0 = row0 + wm + mt * 16 + g;
#pragma unroll
        for (int nt = 0; nt < 8; nt++) {
            int col = col0 + wn + nt * 8 + 2 * qc;
            float b0 = bias[col], b1 = bias[col + 1];
            if (r0 < M) {
                float2 v = make_float2(acc[mt][nt][0] + b0, acc[mt][nt][1] + b1);
                if (RELU) { v.x = fmaxf(v.x, 0.f); v.y = fmaxf(v.y, 0.f); }
                *(float2*)(C + (size_t)r0 * N + col) = v;
            }
            if (r0 + 8 < M) {
                float2 v = make_float2(acc[mt][nt][2] + b0, acc[mt][nt][3] + b1);
                if (RELU) { v.x = fmaxf(v.x, 0.f); v.y = fmaxf(v.y, 0.f); }
                *(float2*)(C + (size_t)(r0 + 8) * N + col) = v;
            }
        }
    }
}

// =====================================================================
// Fused transposes of all 4 weight matrices (+tf32 rounding).
// blockIdx.z selects matrix; oversized grids early-exit.
// =====================================================================
__global__ void transpose_all_kernel(const float* __restrict__ Wv, const float* __restrict__ Wo,
                                     const float* __restrict__ W1, const float* __restrict__ W2,
                                     float* __restrict__ WvT, float* __restrict__ WoT,
                                     float* __restrict__ W1T, float* __restrict__ W2T)
{
    __shared__ float t[32][33];
    int z = blockIdx.z;
    const float* src; float* dst; int R, C;
    if (z == 0)      { src = Wv; dst = WvT; R = 256;  C = 256;  }
    else if (z == 1) { src = Wo; dst = WoT; R = 256;  C = 256;  }
    else if (z == 2) { src = W1; dst = W1T; R = 256;  C = 1024; }
    else             { src = W2; dst = W2T; R = 1024; C = 256;  }

    int bx = blockIdx.x * 32, by = blockIdx.y * 32;
    if (bx >= C || by >= R) return;
#pragma unroll
    for (int i = 0; i < 32; i += 8) {
        int r = by + threadIdx.y + i, c = bx + threadIdx.x;
        if (r < R && c < C)
            t[threadIdx.y + i][threadIdx.x] = __uint_as_float(f2tf32(src[(size_t)r * C + c]));
    }
    __syncthreads();
#pragma unroll
    for (int i = 0; i < 32; i += 8) {
        int r = bx + threadIdx.y + i, c = by + threadIdx.x;
        if (r < C && c < R) dst[(size_t)r * R + c] = t[threadIdx.x][threadIdx.y + i];
    }
}

// =====================================================================
// Top-4 over 7x7 window of (w*mask + b), pad=0, stable ties (lower idx).
// =====================================================================
__global__ void topk_kernel(const float* __restrict__ m0, const float* __restrict__ m1,
                            const float* __restrict__ m2, const float* __restrict__ m3,
                            const float* __restrict__ pmw, const float* __restrict__ pmb)
{
    int t = blockIdx.x * blockDim.x + threadIdx.x;
    if (t >= MROWS * NH) return;
    int h = t % NH;
    int r = t / NH;
    int q = r % LEN;
    int b = r / LEN;

    int l, Wl, s0;
    const float* mk;
    if (q < 8464)        { l = 0; Wl = 92; s0 = 0;     mk = m0; }
    else if (q < 10580)  { l = 1; Wl = 46; s0 = 8464;  mk = m1; }
    else if (q < 11109)  { l = 2; Wl = 23; s0 = 10580; mk = m2; }
    else                 { l = 3; Wl = 12; s0 = 11109; mk = m3; }
    int Hl = Wl;
    int pos = q - s0;
    int y = pos / Wl, x = pos % Wl;

    float w  = pmw[l * NH + h];
    float bb = pmb[l * NH + h];
    const float* mb = mk + (size_t)b * Hl * Wl;

    float tv[4] = {-1e30f, -1e30f, -1e30f, -1e30f};
    int   ti[4] = {0, 0, 0, 0};

    for (int i = 0; i < 7; i++) {
        int yy = y + i - 3;
        for (int j = 0; j < 7; j++) {
            int xx = x + j - 3;
            float val = 0.0f;
            if (yy >= 0 && yy < Hl && xx >= 0 && xx < Wl)
                val = fmaf(mb[yy * Wl + xx], w, bb);
            if (val > tv[3]) {
                int k = i * 7 + j;
                tv[3] = val; ti[3] = k;
                if (tv[3] > tv[2]) { float fv = tv[2]; tv[2] = tv[3]; tv[3] = fv; int iv = ti[2]; ti[2] = ti[3]; ti[3] = iv; }
                if (tv[2] > tv[1]) { float fv = tv[1]; tv[1] = tv[2]; tv[2] = fv; int iv = ti[1]; ti[1] = ti[2]; ti[2] = iv; }
                if (tv[1] > tv[0]) { float fv = tv[0]; tv[0] = tv[1]; tv[1] = fv; int iv = ti[0]; ti[0] = ti[1]; ti[1] = iv; }
            }
        }
    }

    float mx = tv[0];
    float e0 = expf(tv[0] - mx), e1 = expf(tv[1] - mx),
          e2 = expf(tv[2] - mx), e3 = expf(tv[3] - mx);
    float inv = 1.0f / (4.0f * (e0 + e1 + e2 + e3));

    int base = (r * NH + h) * NP;
    float ee[4] = {e0, e1, e2, e3};
#pragma unroll
    for (int p = 0; p < 4; p++) {
        g_attw[base + p] = ee[p] * inv;
        g_offs[(size_t)(base + p) * 2 + 0] = (float)(ti[p] % 7 - 3);
        g_offs[(size_t)(base + p) * 2 + 1] = (float)(ti[p] / 7 - 3);
    }
}

// =====================================================================
// Deformable sampling
// =====================================================================
__global__ void sample_kernel(const float* __restrict__ ref)
{
    int r = blockIdx.x;
    int h = threadIdx.x >> 5;
    int lane = threadIdx.x & 31;
    int b = r / LEN;

    const int Hs[4] = {92, 46, 23, 12};
    const int S0[4] = {0, 8464, 10580, 11109};

    int base = (r * NH + h) * NP;
    float acc = 0.0f;

#pragma unroll
    for (int l = 0; l < 4; l++) {
        int   Wi = Hs[l];
        float Wf = (float)Wi;
        float rx = ref[(size_t)(r * NL + l) * 2 + 0];
        float ry = ref[(size_t)(r * NL + l) * 2 + 1];
        const float* vb = g_value + ((size_t)b * LEN + S0[l]) * D + h * DH + lane;

#pragma unroll
        for (int p = 0; p < NP; p++) {
            float wgt = g_attw[base + p];
            float ox  = g_offs[(size_t)(base + p) * 2 + 0];
            float oy  = g_offs[(size_t)(base + p) * 2 + 1];
            float locx = rx + ox / Wf;
            float locy = ry + oy / Wf;
            float xf = locx * Wf - 0.5f;
            float yf = locy * Wf - 0.5f;
            float x0f = floorf(xf), y0f = floorf(yf);
            float tx = xf - x0f, ty = yf - y0f;
            int x0 = (int)x0f, y0 = (int)y0f;
            int x1 = x0 + 1,  y1 = y0 + 1;

            float w00 = (1.0f - tx) * (1.0f - ty);
            float w01 = tx * (1.0f - ty);
            float w10 = (1.0f - tx) * ty;
            float w11 = tx * ty;

            bool vx0 = (x0 >= 0) & (x0 < Wi);
            bool vx1 = (x1 >= 0) & (x1 < Wi);
            bool vy0 = (y0 >= 0) & (y0 < Wi);
            bool vy1 = (y1 >= 0) & (y1 < Wi);

            float s = 0.0f;
            if (vy0 & vx0) s = fmaf(w00, vb[(size_t)(y0 * Wi + x0) * D], s);
            if (vy0 & vx1) s = fmaf(w01, vb[(size_t)(y0 * Wi + x1) * D], s);
            if (vy1 & vx0) s = fmaf(w10, vb[(size_t)(y1 * Wi + x0) * D], s);
            if (vy1 & vx1) s = fmaf(w11, vb[(size_t)(y1 * Wi + x1) * D], s);
            acc = fmaf(wgt, s, acc);
        }
    }
    g_attnout[(size_t)r * D + h * DH + lane] = acc;
}

// =====================================================================
// out = LayerNorm(a + res) * g + b
// =====================================================================
__global__ void add_ln_kernel(const float* __restrict__ a, const float* __restrict__ res,
                              const float* __restrict__ gg, const float* __restrict__ bb,
                              float* __restrict__ out)
{
    int row = blockIdx.x;
    int t = threadIdx.x;
    float v = a[(size_t)row * D + t] + res[(size_t)row * D + t];

    __shared__ float s1[8], s2[8];
    float s = v, u = v * v;
#pragma unroll
    for (int o = 16; o; o >>= 1) {
        s += __shfl_xor_sync(0xffffffffu, s, o);
        u += __shfl_xor_sync(0xffffffffu, u, o);
    }
    if ((t & 31) == 0) { s1[t >> 5] = s; s2[t >> 5] = u; }
    __syncthreads();
    float sum = 0.f, sq = 0.f;
#pragma unroll
    for (int i = 0; i < 8; i++) { sum += s1[i]; sq += s2[i]; }
    float mean = sum * (1.0f / D);
    float var  = sq * (1.0f / D) - mean * mean;
    float rs = rsqrtf(var + 1e-5f);
    out[(size_t)row * D + t] = (v - mean) * rs * gg[t] + bb[t];
}

// =====================================================================
extern "C" void kernel_launch(void* const* d_in, const int* in_sizes, int n_in,
                              void* d_out, int out_size)
{
    const float* src  = (const float*)d_in[0];
    const float* ref  = (const float*)d_in[2];
    const float* m0   = (const float*)d_in[4];
    const float* m1   = (const float*)d_in[5];
    const float* m2   = (const float*)d_in[6];
    const float* m3   = (const float*)d_in[7];
    const float* pmw  = (const float*)d_in[10];
    const float* pmb  = (const float*)d_in[11];
    const float* Wv   = (const float*)d_in[12];
    const float* bv   = (const float*)d_in[13];
    const float* Wo   = (const float*)d_in[14];
    const float* bo   = (const float*)d_in[15];
    const float* ln1g = (const float*)d_in[16];
    const float* ln1b = (const float*)d_in[17];
    const float* W1   = (const float*)d_in[18];
    const float* b1   = (const float*)d_in[19];
    const float* W2   = (const float*)d_in[20];
    const float* b2   = (const float*)d_in[21];
    const float* ln2g = (const float*)d_in[22];
    const float* ln2b = (const float*)d_in[23];
    float* out = (float*)d_out;

    float *pv, *pao, *ptmp, *px, *ph, *pWvT, *pWoT, *pW1T, *pW2T;
    cudaGetSymbolAddress((void**)&pv,   g_value);
    cudaGetSymbolAddress((void**)&pao,  g_attnout);
    cudaGetSymbolAddress((void**)&ptmp, g_tmp);
    cudaGetSymbolAddress((void**)&px,   g_x);
    cudaGetSymbolAddress((void**)&ph,   g_hid);
    cudaGetSymbolAddress((void**)&pWvT, g_WvT);
    cudaGetSymbolAddress((void**)&pWoT, g_WoT);
    cudaGetSymbolAddress((void**)&pW1T, g_W1T);
    cudaGetSymbolAddress((void**)&pW2T, g_W2T);

    cudaFuncSetAttribute(gemm_tc<0>, cudaFuncAttributeMaxDynamicSharedMemorySize, GEMM_SMEM);
    cudaFuncSetAttribute(gemm_tc<1>, cudaFuncAttributeMaxDynamicSharedMemorySize, GEMM_SMEM);

    const int MB = (MROWS + 127) / 128;   // 176

    // 0. all weight transposes + tf32 rounding (B^T, K-major), one launch
    transpose_all_kernel<<<dim3(32, 32, 4), dim3(32, 8)>>>(Wv, Wo, W1, W2,
                                                           pWvT, pWoT, pW1T, pW2T);

    // 1. top-k offsets + attention weights
    topk_kernel<<<(MROWS * NH + 255) / 256, 256>>>(m0, m1, m2, m3, pmw, pmb);

    // 2. value = src @ Wv + bv
    gemm_tc<0><<<dim3(2, MB), 128, GEMM_SMEM>>>(src, pWvT, bv, pv, MROWS, 256, 256);

    // 3. deformable bilinear sampling -> attnout (pre-Wo)
    sample_kernel<<<MROWS, 256>>>(ref);

    // 4. attn_out = attnout @ Wo + bo
    gemm_tc<0><<<dim3(2, MB), 128, GEMM_SMEM>>>(pao, pWoT, bo, ptmp, MROWS, 256, 256);

    // 5. x = LN(src + attn_out)
    add_ln_kernel<<<MROWS, 256>>>(ptmp, src, ln1g, ln1b, px);

    // 6. hid = relu(x @ W1 + b1)
    gemm_tc<1><<<dim3(8, MB), 128, GEMM_SMEM>>>(px, pW1T, b1, ph, MROWS, 1024, 256);

    // 7. y = hid @ W2 + b2
    gemm_tc<0><<<dim3(2, MB), 128, GEMM_SMEM>>>(ph, pW2T, b2, ptmp, MROWS, 256, 1024);

    // 8. out = LN(x + y)
    add_ln_kernel<<<MROWS, 256>>>(ptmp, px, ln2g, ln2b, out);
}

// round 5
// speedup vs baseline: 3.0539x; 1.3329x over previous
#include <cuda_runtime.h>
#include <cstdint>
#include <math.h>

#define BS   2
#define LEN  11253
#define MROWS (BS*LEN)   // 22506
#define D    256
#define NH   8
#define NP   4
#define NL   4
#define DH   32
#define DFF  1024

// ---- scratch (device globals; no allocation allowed) ----
__device__ float g_value  [(size_t)MROWS * D];
__device__ float g_attnout[(size_t)MROWS * D];
__device__ float g_tmp    [(size_t)MROWS * D];
__device__ float g_x      [(size_t)MROWS * D];
__device__ float g_hid    [(size_t)MROWS * DFF];
__device__ float g_attw   [(size_t)MROWS * NH * NP];
__device__ float g_offs   [(size_t)MROWS * NH * NP * 2];
__device__ float g_WvT    [D * D];
__device__ float g_WoT    [D * D];
__device__ float g_W1T    [DFF * D];
__device__ float g_W2T    [D * DFF];

// =====================================================================
// helpers
// =====================================================================
__device__ __forceinline__ uint32_t f2tf32(float x) {
    uint32_t r;
    asm("cvt.rna.tf32.f32 %0, %1;" : "=r"(r) : "f"(x));
    return r;
}
__device__ __forceinline__ void mma_tf32(float* d, const uint32_t* a, const uint32_t* b) {
    asm volatile(
        "mma.sync.aligned.m16n8k8.row.col.f32.tf32.tf32.f32 "
        "{%0,%1,%2,%3}, {%4,%5,%6,%7}, {%8,%9}, {%0,%1,%2,%3};"
        : "+f"(d[0]), "+f"(d[1]), "+f"(d[2]), "+f"(d[3])
        : "r"(a[0]), "r"(a[1]), "r"(a[2]), "r"(a[3]), "r"(b[0]), "r"(b[1]));
}

// =====================================================================
// TF32 tensor-core GEMM: C[M,N] = A[M,K] @ BT[N,K]^T + bias (opt relu)
// 128x128 CTA tile, BK=32, 3-stage cp.async, 4 warps (2x2), 64x64/warp.
// =====================================================================
#define SSTRIDE     36
#define TILE_F      (128*SSTRIDE)
#define STAGE_F     (2*TILE_F)
#define GEMM_SMEM   (3*STAGE_F*4)         // 110592 B

template<int RELU>
__global__ void __launch_bounds__(128, 2)
gemm_tc(const float* __restrict__ A, const float* __restrict__ BT,
        const float* __restrict__ bias, float* __restrict__ C,
        int M, int N, int K)
{
    extern __shared__ float smem[];
    int tid = threadIdx.x, wid = tid >> 5, lane = tid & 31;
    int g = lane >> 2, qc = lane & 3;
    int row0 = blockIdx.y * 128, col0 = blockIdx.x * 128;
    int wm = (wid & 1) * 64, wn = (wid >> 1) * 64;

    const int NC = K >> 5;

    auto load_chunk = [&](int c) {
        if (c >= NC) { asm volatile("cp.async.commit_group;"); return; }
        float* As = smem + (c % 3) * STAGE_F;
        float* Bs = As + TILE_F;
        int k0 = c * 32;
        const float* Ab = A + (size_t)row0 * K + k0;
        const float* Bb = BT + (size_t)col0 * K + k0;
        uint32_t a_st, b_st;
        asm("{ .reg .u64 t; cvta.to.shared.u64 t, %1; cvt.u32.u64 %0, t; }" : "=r"(a_st) : "l"(As));
        asm("{ .reg .u64 t; cvta.to.shared.u64 t, %1; cvt.u32.u64 %0, t; }" : "=r"(b_st) : "l"(Bs));
#pragma unroll
        for (int i = 0; i < 8; i++) {
            int f4 = tid + i * 128;
            int r = f4 >> 3, c4 = f4 & 7;
            uint32_t off = (uint32_t)(r * SSTRIDE + c4 * 4) * 4;
            uint32_t nbytes = (row0 + r < M) ? 16u : 0u;
            asm volatile("cp.async.cg.shared.global [%0], [%1], 16, %2;"
                :: "r"(a_st + off), "l"(Ab + (size_t)r * K + c4 * 4), "r"(nbytes));
            asm volatile("cp.async.cg.shared.global [%0], [%1], 16;"
                :: "r"(b_st + off), "l"(Bb + (size_t)r * K + c4 * 4));
        }
        asm volatile("cp.async.commit_group;");
    };

    float acc[4][8][4];
#pragma unroll
    for (int mt = 0; mt < 4; mt++)
#pragma unroll
        for (int nt = 0; nt < 8; nt++)
#pragma unroll
            for (int i = 0; i < 4; i++) acc[mt][nt][i] = 0.0f;

    load_chunk(0);
    load_chunk(1);

    for (int c = 0; c < NC; c++) {
        asm volatile("cp.async.wait_group 1;");
        __syncthreads();
        load_chunk(c + 2);

        const float* As = smem + (c % 3) * STAGE_F;
        const float* Bs = As + TILE_F;
#pragma unroll
        for (int ks = 0; ks < 4; ks++) {
            int k0 = ks * 8 + qc;
            uint32_t af[4][4];
#pragma unroll
            for (int mt = 0; mt < 4; mt++) {
                int r = wm + mt * 16 + g;
                af[mt][0] = f2tf32(As[r * SSTRIDE + k0]);
                af[mt][1] = f2tf32(As[(r + 8) * SSTRIDE + k0]);
                af[mt][2] = f2tf32(As[r * SSTRIDE + k0 + 4]);
                af[mt][3] = f2tf32(As[(r + 8) * SSTRIDE + k0 + 4]);
            }
            uint32_t bf[8][2];
#pragma unroll
            for (int nt = 0; nt < 8; nt++) {
                int n = wn + nt * 8 + g;
                bf[nt][0] = __float_as_uint(Bs[n * SSTRIDE + k0]);
                bf[nt][1] = __float_as_uint(Bs[n * SSTRIDE + k0 + 4]);
            }
#pragma unroll
            for (int mt = 0; mt < 4; mt++)
#pragma unroll
                for (int nt = 0; nt < 8; nt++)
                    mma_tf32(acc[mt][nt], af[mt], bf[nt]);
        }
    }

    // epilogue
#pragma unroll
    for (int mt = 0; mt < 4; mt++) {
        int r0 = row0 + wm + mt * 16 + g;
#pragma unroll
        for (int nt = 0; nt < 8; nt++) {
            int col = col0 + wn + nt * 8 + 2 * qc;
            float b0 = bias[col], b1 = bias[col + 1];
            if (r0 < M) {
                float2 v = make_float2(acc[mt][nt][0] + b0, acc[mt][nt][1] + b1);
                if (RELU) { v.x = fmaxf(v.x, 0.f); v.y = fmaxf(v.y, 0.f); }
                *(float2*)(C + (size_t)r0 * N + col) = v;
            }
            if (r0 + 8 < M) {
                float2 v = make_float2(acc[mt][nt][2] + b0, acc[mt][nt][3] + b1);
                if (RELU) { v.x = fmaxf(v.x, 0.f); v.y = fmaxf(v.y, 0.f); }
                *(float2*)(C + (size_t)(r0 + 8) * N + col) = v;
            }
        }
    }
}

// =====================================================================
// Fused transposes of all 4 weight matrices (+tf32 rounding).
// =====================================================================
__global__ void transpose_all_kernel(const float* __restrict__ Wv, const float* __restrict__ Wo,
                                     const float* __restrict__ W1, const float* __restrict__ W2,
                                     float* __restrict__ WvT, float* __restrict__ WoT,
                                     float* __restrict__ W1T, float* __restrict__ W2T)
{
    __shared__ float t[32][33];
    int z = blockIdx.z;
    const float* src; float* dst; int R, C;
    if (z == 0)      { src = Wv; dst = WvT; R = 256;  C = 256;  }
    else if (z == 1) { src = Wo; dst = WoT; R = 256;  C = 256;  }
    else if (z == 2) { src = W1; dst = W1T; R = 256;  C = 1024; }
    else             { src = W2; dst = W2T; R = 1024; C = 256;  }

    int bx = blockIdx.x * 32, by = blockIdx.y * 32;
    if (bx >= C || by >= R) return;
#pragma unroll
    for (int i = 0; i < 32; i += 8) {
        int r = by + threadIdx.y + i, c = bx + threadIdx.x;
        if (r < R && c < C)
            t[threadIdx.y + i][threadIdx.x] = __uint_as_float(f2tf32(src[(size_t)r * C + c]));
    }
    __syncthreads();
#pragma unroll
    for (int i = 0; i < 32; i += 8) {
        int r = bx + threadIdx.y + i, c = by + threadIdx.x;
        if (r < C && c < R) dst[(size_t)r * R + c] = t[threadIdx.x][threadIdx.y + i];
    }
}

// =====================================================================
// Top-4 over 7x7 window of (w*mask + b), pad=0, stable ties (lower idx).
// =====================================================================
__global__ void topk_kernel(const float* __restrict__ m0, const float* __restrict__ m1,
                            const float* __restrict__ m2, const float* __restrict__ m3,
                            const float* __restrict__ pmw, const float* __restrict__ pmb)
{
    int t = blockIdx.x * blockDim.x + threadIdx.x;
    if (t >= MROWS * NH) return;
    int h = t % NH;
    int r = t / NH;
    int q = r % LEN;
    int b = r / LEN;

    int l, Wl, s0;
    const float* mk;
    if (q < 8464)        { l = 0; Wl = 92; s0 = 0;     mk = m0; }
    else if (q < 10580)  { l = 1; Wl = 46; s0 = 8464;  mk = m1; }
    else if (q < 11109)  { l = 2; Wl = 23; s0 = 10580; mk = m2; }
    else                 { l = 3; Wl = 12; s0 = 11109; mk = m3; }
    int Hl = Wl;
    int pos = q - s0;
    int y = pos / Wl, x = pos % Wl;

    float w  = pmw[l * NH + h];
    float bb = pmb[l * NH + h];
    const float* mb = mk + (size_t)b * Hl * Wl;

    float tv[4] = {-1e30f, -1e30f, -1e30f, -1e30f};
    int   ti[4] = {0, 0, 0, 0};

    for (int i = 0; i < 7; i++) {
        int yy = y + i - 3;
        for (int j = 0; j < 7; j++) {
            int xx = x + j - 3;
            float val = 0.0f;
            if (yy >= 0 && yy < Hl && xx >= 0 && xx < Wl)
                val = fmaf(mb[yy * Wl + xx], w, bb);
            if (val > tv[3]) {
                int k = i * 7 + j;
                tv[3] = val; ti[3] = k;
                if (tv[3] > tv[2]) { float fv = tv[2]; tv[2] = tv[3]; tv[3] = fv; int iv = ti[2]; ti[2] = ti[3]; ti[3] = iv; }
                if (tv[2] > tv[1]) { float fv = tv[1]; tv[1] = tv[2]; tv[2] = fv; int iv = ti[1]; ti[1] = ti[2]; ti[2] = iv; }
                if (tv[1] > tv[0]) { float fv = tv[0]; tv[0] = tv[1]; tv[1] = fv; int iv = ti[0]; ti[0] = ti[1]; ti[1] = iv; }
            }
        }
    }

    float mx = tv[0];
    float e0 = expf(tv[0] - mx), e1 = expf(tv[1] - mx),
          e2 = expf(tv[2] - mx), e3 = expf(tv[3] - mx);
    float inv = 1.0f / (4.0f * (e0 + e1 + e2 + e3));

    int base = (r * NH + h) * NP;
    float ee[4] = {e0, e1, e2, e3};
#pragma unroll
    for (int p = 0; p < 4; p++) {
        g_attw[base + p] = ee[p] * inv;
        g_offs[(size_t)(base + p) * 2 + 0] = (float)(ti[p] % 7 - 3);
        g_offs[(size_t)(base + p) * 2 + 1] = (float)(ti[p] / 7 - 3);
    }
}

// =====================================================================
// Deformable sampling, warp-specialized:
// block = one query r; warp = one head. Lanes 0-15 compute the 16
// (level,point) combos' indices+folded weights once (scalar phase, smem);
// then all 32 lanes (channels) do broadcast-LDS + gather + FMA only.
// =====================================================================
__global__ void __launch_bounds__(256)
sample_kernel(const float* __restrict__ ref)
{
    __shared__ float s_w[8][16][4];
    __shared__ int   s_i[8][16][4];

    int r = blockIdx.x;
    int wid = threadIdx.x >> 5, lane = threadIdx.x & 31;
    int b = r / LEN;

    if (lane < 16) {
        const int HsA[4] = {92, 46, 23, 12};
        const int S0A[4] = {0, 8464, 10580, 11109};
        int l = lane >> 2, p = lane & 3;
        int Wi = HsA[l];
        float Wf = (float)Wi;

        float rx = ref[(size_t)(r * NL + l) * 2 + 0];
        float ry = ref[(size_t)(r * NL + l) * 2 + 1];
        int base = (r * NH + wid) * NP + p;
        float wgt = g_attw[base];
        float ox  = g_offs[(size_t)base * 2 + 0];
        float oy  = g_offs[(size_t)base * 2 + 1];

        float locx = rx + ox / Wf;
        float locy = ry + oy / Wf;
        float xf = locx * Wf - 0.5f;
        float yf = locy * Wf - 0.5f;
        float x0f = floorf(xf), y0f = floorf(yf);
        float tx = xf - x0f, ty = yf - y0f;
        int x0 = (int)x0f, y0 = (int)y0f;
        int x1 = x0 + 1,  y1 = y0 + 1;

        float w00 = (1.0f - tx) * (1.0f - ty) * wgt;
        float w01 = tx * (1.0f - ty) * wgt;
        float w10 = (1.0f - tx) * ty * wgt;
        float w11 = tx * ty * wgt;

        bool vx0 = (x0 >= 0) & (x0 < Wi);
        bool vx1 = (x1 >= 0) & (x1 < Wi);
        bool vy0 = (y0 >= 0) & (y0 < Wi);
        bool vy1 = (y1 >= 0) & (y1 < Wi);

        int x0c = min(max(x0, 0), Wi - 1), x1c = min(max(x1, 0), Wi - 1);
        int y0c = min(max(y0, 0), Wi - 1), y1c = min(max(y1, 0), Wi - 1);
        int rb = b * LEN + S0A[l];

        s_w[wid][lane][0] = (vy0 & vx0) ? w00 : 0.0f;
        s_w[wid][lane][1] = (vy0 & vx1) ? w01 : 0.0f;
        s_w[wid][lane][2] = (vy1 & vx0) ? w10 : 0.0f;
        s_w[wid][lane][3] = (vy1 & vx1) ? w11 : 0.0f;
        s_i[wid][lane][0] = rb + y0c * Wi + x0c;
        s_i[wid][lane][1] = rb + y0c * Wi + x1c;
        s_i[wid][lane][2] = rb + y1c * Wi + x0c;
        s_i[wid][lane][3] = rb + y1c * Wi + x1c;
    }
    __syncwarp();

    const float* vb = g_value + wid * DH + lane;
    float acc = 0.0f;
#pragma unroll
    for (int c = 0; c < 16; c++) {
        float4 w  = *(const float4*)s_w[wid][c];
        int4   ii = *(const int4*)s_i[wid][c];
        if (w.x != 0.0f) acc = fmaf(w.x, vb[(size_t)ii.x * D], acc);
        if (w.y != 0.0f) acc = fmaf(w.y, vb[(size_t)ii.y * D], acc);
        if (w.z != 0.0f) acc = fmaf(w.z, vb[(size_t)ii.z * D], acc);
        if (w.w != 0.0f) acc = fmaf(w.w, vb[(size_t)ii.w * D], acc);
    }
    g_attnout[(size_t)r * D + wid * DH + lane] = acc;
}

// =====================================================================
// out = LayerNorm(a + res) * g + b
// =====================================================================
__global__ void add_ln_kernel(const float* __restrict__ a, const float* __restrict__ res,
                              const float* __restrict__ gg, const float* __restrict__ bb,
                              float* __restrict__ out)
{
    int row = blockIdx.x;
    int t = threadIdx.x;
    float v = a[(size_t)row * D + t] + res[(size_t)row * D + t];

    __shared__ float s1[8], s2[8];
    float s = v, u = v * v;
#pragma unroll
    for (int o = 16; o; o >>= 1) {
        s += __shfl_xor_sync(0xffffffffu, s, o);
        u += __shfl_xor_sync(0xffffffffu, u, o);
    }
    if ((t & 31) == 0) { s1[t >> 5] = s; s2[t >> 5] = u; }
    __syncthreads();
    float sum = 0.f, sq = 0.f;
#pragma unroll
    for (int i = 0; i < 8; i++) { sum += s1[i]; sq += s2[i]; }
    float mean = sum * (1.0f / D);
    float var  = sq * (1.0f / D) - mean * mean;
    float rs = rsqrtf(var + 1e-5f);
    out[(size_t)row * D + t] = (v - mean) * rs * gg[t] + bb[t];
}

// =====================================================================
extern "C" void kernel_launch(void* const* d_in, const int* in_sizes, int n_in,
                              void* d_out, int out_size)
{
    const float* src  = (const float*)d_in[0];
    const float* ref  = (const float*)d_in[2];
    const float* m0   = (const float*)d_in[4];
    const float* m1   = (const float*)d_in[5];
    const float* m2   = (const float*)d_in[6];
    const float* m3   = (const float*)d_in[7];
    const float* pmw  = (const float*)d_in[10];
    const float* pmb  = (const float*)d_in[11];
    const float* Wv   = (const float*)d_in[12];
    const float* bv   = (const float*)d_in[13];
    const float* Wo   = (const float*)d_in[14];
    const float* bo   = (const float*)d_in[15];
    const float* ln1g = (const float*)d_in[16];
    const float* ln1b = (const float*)d_in[17];
    const float* W1   = (const float*)d_in[18];
    const float* b1   = (const float*)d_in[19];
    const float* W2   = (const float*)d_in[20];
    const float* b2   = (const float*)d_in[21];
    const float* ln2g = (const float*)d_in[22];
    const float* ln2b = (const float*)d_in[23];
    float* out = (float*)d_out;

    float *pv, *pao, *ptmp, *px, *ph, *pWvT, *pWoT, *pW1T, *pW2T;
    cudaGetSymbolAddress((void**)&pv,   g_value);
    cudaGetSymbolAddress((void**)&pao,  g_attnout);
    cudaGetSymbolAddress((void**)&ptmp, g_tmp);
    cudaGetSymbolAddress((void**)&px,   g_x);
    cudaGetSymbolAddress((void**)&ph,   g_hid);
    cudaGetSymbolAddress((void**)&pWvT, g_WvT);
    cudaGetSymbolAddress((void**)&pWoT, g_WoT);
    cudaGetSymbolAddress((void**)&pW1T, g_W1T);
    cudaGetSymbolAddress((void**)&pW2T, g_W2T);

    cudaFuncSetAttribute(gemm_tc<0>, cudaFuncAttributeMaxDynamicSharedMemorySize, GEMM_SMEM);
    cudaFuncSetAttribute(gemm_tc<1>, cudaFuncAttributeMaxDynamicSharedMemorySize, GEMM_SMEM);

    const int MB = (MROWS + 127) / 128;   // 176

    // 0. all weight transposes + tf32 rounding (B^T, K-major), one launch
    transpose_all_kernel<<<dim3(32, 32, 4), dim3(32, 8)>>>(Wv, Wo, W1, W2,
                                                           pWvT, pWoT, pW1T, pW2T);

    // 1. top-k offsets + attention weights
    topk_kernel<<<(MROWS * NH + 255) / 256, 256>>>(m0, m1, m2, m3, pmw, pmb);

    // 2. value = src @ Wv + bv
    gemm_tc<0><<<dim3(2, MB), 128, GEMM_SMEM>>>(src, pWvT, bv, pv, MROWS, 256, 256);

    // 3. deformable bilinear sampling -> attnout (pre-Wo)
    sample_kernel<<<MROWS, 256>>>(ref);

    // 4. attn_out = attnout @ Wo + bo
    gemm_tc<0><<<dim3(2, MB), 128, GEMM_SMEM>>>(pao, pWoT, bo, ptmp, MROWS, 256, 256);

    // 5. x = LN(src + attn_out)
    add_ln_kernel<<<MROWS, 256>>>(ptmp, src, ln1g, ln1b, px);

    // 6. hid = relu(x @ W1 + b1)
    gemm_tc<1><<<dim3(8, MB), 128, GEMM_SMEM>>>(px, pW1T, b1, ph, MROWS, 1024, 256);

    // 7. y = hid @ W2 + b2
    gemm_tc<0><<<dim3(2, MB), 128, GEMM_SMEM>>>(ph, pW2T, b2, ptmp, MROWS, 256, 1024);

    // 8. out = LN(x + y)
    add_ln_kernel<<<MROWS, 256>>>(ptmp, px, ln2g, ln2b, out);
}

// round 6
// speedup vs baseline: 3.1120x; 1.0190x over previous
#include <cuda_runtime.h>
#include <cstdint>
#include <math.h>

#define BS   2
#define LEN  11253
#define MROWS (BS*LEN)   // 22506
#define D    256
#define NH   8
#define NP   4
#define NL   4
#define DH   32
#define DFF  1024

// ---- scratch (device globals; no allocation allowed) ----
__device__ float g_value  [(size_t)MROWS * D];
__device__ float g_attnout[(size_t)MROWS * D];
__device__ float g_tmp    [(size_t)MROWS * D];
__device__ float g_x      [(size_t)MROWS * D];
__device__ float g_xr     [(size_t)MROWS * D];
__device__ float g_hid    [(size_t)MROWS * DFF];
__device__ float g_attw   [(size_t)MROWS * NH * NP];
__device__ float g_offs   [(size_t)MROWS * NH * NP * 2];
__device__ float g_WvT    [D * D];
__device__ float g_WoT    [D * D];
__device__ float g_W1T    [DFF * D];
__device__ float g_W2T    [D * DFF];

// =====================================================================
// helpers
// =====================================================================
__device__ __forceinline__ uint32_t f2tf32(float x) {
    uint32_t r;
    asm("cvt.rna.tf32.f32 %0, %1;" : "=r"(r) : "f"(x));
    return r;
}
__device__ __forceinline__ void mma_tf32(float* d, const uint32_t* a, const uint32_t* b) {
    asm volatile(
        "mma.sync.aligned.m16n8k8.row.col.f32.tf32.tf32.f32 "
        "{%0,%1,%2,%3}, {%4,%5,%6,%7}, {%8,%9}, {%0,%1,%2,%3};"
        : "+f"(d[0]), "+f"(d[1]), "+f"(d[2]), "+f"(d[3])
        : "r"(a[0]), "r"(a[1]), "r"(a[2]), "r"(a[3]), "r"(b[0]), "r"(b[1]));
}

// =====================================================================
// TF32 tensor-core GEMM: C[M,N] = A[M,K] @ BT[N,K]^T + bias (opt relu)
// 128x128 CTA tile, BK=32, 3-stage cp.async, 4 warps (2x2), 64x64/warp.
// CVTA: round A fragments to tf32 at load (else A is pre-rounded).
// ROUND: round output stores to tf32 (consumer is another tf32 GEMM).
// =====================================================================
#define SSTRIDE     36
#define TILE_F      (128*SSTRIDE)
#define STAGE_F     (2*TILE_F)
#define GEMM_SMEM   (3*STAGE_F*4)         // 110592 B

template<int RELU, int CVTA, int ROUND>
__global__ void __launch_bounds__(128, 2)
gemm_tc(const float* __restrict__ A, const float* __restrict__ BT,
        const float* __restrict__ bias, float* __restrict__ C,
        int M, int N, int K)
{
    extern __shared__ float smem[];
    int tid = threadIdx.x, wid = tid >> 5, lane = tid & 31;
    int g = lane >> 2, qc = lane & 3;
    int row0 = blockIdx.y * 128, col0 = blockIdx.x * 128;
    int wm = (wid & 1) * 64, wn = (wid >> 1) * 64;

    const int NC = K >> 5;

    auto load_chunk = [&](int c) {
        if (c >= NC) { asm volatile("cp.async.commit_group;"); return; }
        float* As = smem + (c % 3) * STAGE_F;
        float* Bs = As + TILE_F;
        int k0 = c * 32;
        const float* Ab = A + (size_t)row0 * K + k0;
        const float* Bb = BT + (size_t)col0 * K + k0;
        uint32_t a_st, b_st;
        asm("{ .reg .u64 t; cvta.to.shared.u64 t, %1; cvt.u32.u64 %0, t; }" : "=r"(a_st) : "l"(As));
        asm("{ .reg .u64 t; cvta.to.shared.u64 t, %1; cvt.u32.u64 %0, t; }" : "=r"(b_st) : "l"(Bs));
#pragma unroll
        for (int i = 0; i < 8; i++) {
            int f4 = tid + i * 128;
            int r = f4 >> 3, c4 = f4 & 7;
            uint32_t off = (uint32_t)(r * SSTRIDE + c4 * 4) * 4;
            uint32_t nbytes = (row0 + r < M) ? 16u : 0u;
            asm volatile("cp.async.cg.shared.global [%0], [%1], 16, %2;"
                :: "r"(a_st + off), "l"(Ab + (size_t)r * K + c4 * 4), "r"(nbytes));
            asm volatile("cp.async.cg.shared.global [%0], [%1], 16;"
                :: "r"(b_st + off), "l"(Bb + (size_t)r * K + c4 * 4));
        }
        asm volatile("cp.async.commit_group;");
    };

    float acc[4][8][4];
#pragma unroll
    for (int mt = 0; mt < 4; mt++)
#pragma unroll
        for (int nt = 0; nt < 8; nt++)
#pragma unroll
            for (int i = 0; i < 4; i++) acc[mt][nt][i] = 0.0f;

    load_chunk(0);
    load_chunk(1);

    for (int c = 0; c < NC; c++) {
        asm volatile("cp.async.wait_group 1;");
        __syncthreads();
        load_chunk(c + 2);

        const float* As = smem + (c % 3) * STAGE_F;
        const float* Bs = As + TILE_F;
#pragma unroll
        for (int ks = 0; ks < 4; ks++) {
            int k0 = ks * 8 + qc;
            uint32_t af[4][4];
#pragma unroll
            for (int mt = 0; mt < 4; mt++) {
                int r = wm + mt * 16 + g;
                if (CVTA) {
                    af[mt][0] = f2tf32(As[r * SSTRIDE + k0]);
                    af[mt][1] = f2tf32(As[(r + 8) * SSTRIDE + k0]);
                    af[mt][2] = f2tf32(As[r * SSTRIDE + k0 + 4]);
                    af[mt][3] = f2tf32(As[(r + 8) * SSTRIDE + k0 + 4]);
                } else {
                    af[mt][0] = __float_as_uint(As[r * SSTRIDE + k0]);
                    af[mt][1] = __float_as_uint(As[(r + 8) * SSTRIDE + k0]);
                    af[mt][2] = __float_as_uint(As[r * SSTRIDE + k0 + 4]);
                    af[mt][3] = __float_as_uint(As[(r + 8) * SSTRIDE + k0 + 4]);
                }
            }
            uint32_t bf[8][2];
#pragma unroll
            for (int nt = 0; nt < 8; nt++) {
                int n = wn + nt * 8 + g;
                bf[nt][0] = __float_as_uint(Bs[n * SSTRIDE + k0]);
                bf[nt][1] = __float_as_uint(Bs[n * SSTRIDE + k0 + 4]);
            }
#pragma unroll
            for (int mt = 0; mt < 4; mt++)
#pragma unroll
                for (int nt = 0; nt < 8; nt++)
                    mma_tf32(acc[mt][nt], af[mt], bf[nt]);
        }
    }

    // epilogue
#pragma unroll
    for (int mt = 0; mt < 4; mt++) {
        int r0 = row0 + wm + mt * 16 + g;
#pragma unroll
        for (int nt = 0; nt < 8; nt++) {
            int col = col0 + wn + nt * 8 + 2 * qc;
            float b0 = bias[col], b1 = bias[col + 1];
#pragma unroll
            for (int half = 0; half < 2; half++) {
                int rr = r0 + half * 8;
                if (rr < M) {
                    float vx = acc[mt][nt][half * 2 + 0] + b0;
                    float vy = acc[mt][nt][half * 2 + 1] + b1;
                    if (RELU) { vx = fmaxf(vx, 0.f); vy = fmaxf(vy, 0.f); }
                    float2 v;
                    if (ROUND) {
                        v.x = __uint_as_float(f2tf32(vx));
                        v.y = __uint_as_float(f2tf32(vy));
                    } else { v.x = vx; v.y = vy; }
                    *(float2*)(C + (size_t)rr * N + col) = v;
                }
            }
        }
    }
}

// =====================================================================
// Fused transposes of all 4 weight matrices (+tf32 rounding).
// =====================================================================
__global__ void transpose_all_kernel(const float* __restrict__ Wv, const float* __restrict__ Wo,
                                     const float* __restrict__ W1, const float* __restrict__ W2,
                                     float* __restrict__ WvT, float* __restrict__ WoT,
                                     float* __restrict__ W1T, float* __restrict__ W2T)
{
    __shared__ float t[32][33];
    int z = blockIdx.z;
    const float* src; float* dst; int R, C;
    if (z == 0)      { src = Wv; dst = WvT; R = 256;  C = 256;  }
    else if (z == 1) { src = Wo; dst = WoT; R = 256;  C = 256;  }
    else if (z == 2) { src = W1; dst = W1T; R = 256;  C = 1024; }
    else             { src = W2; dst = W2T; R = 1024; C = 256;  }

    int bx = blockIdx.x * 32, by = blockIdx.y * 32;
    if (bx >= C || by >= R) return;
#pragma unroll
    for (int i = 0; i < 32; i += 8) {
        int r = by + threadIdx.y + i, c = bx + threadIdx.x;
        if (r < R && c < C)
            t[threadIdx.y + i][threadIdx.x] = __uint_as_float(f2tf32(src[(size_t)r * C + c]));
    }
    __syncthreads();
#pragma unroll
    for (int i = 0; i < 32; i += 8) {
        int r = bx + threadIdx.y + i, c = by + threadIdx.x;
        if (r < C && c < R) dst[(size_t)r * R + c] = t[threadIdx.x][threadIdx.y + i];
    }
}

// =====================================================================
// Top-4 over 7x7 window of (w*mask + b), pad=0, stable ties (lower idx).
// =====================================================================
__global__ void topk_kernel(const float* __restrict__ m0, const float* __restrict__ m1,
                            const float* __restrict__ m2, const float* __restrict__ m3,
                            const float* __restrict__ pmw, const float* __restrict__ pmb)
{
    int t = blockIdx.x * blockDim.x + threadIdx.x;
    if (t >= MROWS * NH) return;
    int h = t % NH;
    int r = t / NH;
    int q = r % LEN;
    int b = r / LEN;

    int l, Wl, s0;
    const float* mk;
    if (q < 8464)        { l = 0; Wl = 92; s0 = 0;     mk = m0; }
    else if (q < 10580)  { l = 1; Wl = 46; s0 = 8464;  mk = m1; }
    else if (q < 11109)  { l = 2; Wl = 23; s0 = 10580; mk = m2; }
    else                 { l = 3; Wl = 12; s0 = 11109; mk = m3; }
    int Hl = Wl;
    int pos = q - s0;
    int y = pos / Wl, x = pos % Wl;

    float w  = pmw[l * NH + h];
    float bb = pmb[l * NH + h];
    const float* mb = mk + (size_t)b * Hl * Wl;

    float tv[4] = {-1e30f, -1e30f, -1e30f, -1e30f};
    int   ti[4] = {0, 0, 0, 0};

    for (int i = 0; i < 7; i++) {
        int yy = y + i - 3;
        for (int j = 0; j < 7; j++) {
            int xx = x + j - 3;
            float val = 0.0f;
            if (yy >= 0 && yy < Hl && xx >= 0 && xx < Wl)
                val = fmaf(mb[yy * Wl + xx], w, bb);
            if (val > tv[3]) {
                int k = i * 7 + j;
                tv[3] = val; ti[3] = k;
                if (tv[3] > tv[2]) { float fv = tv[2]; tv[2] = tv[3]; tv[3] = fv; int iv = ti[2]; ti[2] = ti[3]; ti[3] = iv; }
                if (tv[2] > tv[1]) { float fv = tv[1]; tv[1] = tv[2]; tv[2] = fv; int iv = ti[1]; ti[1] = ti[2]; ti[2] = iv; }
                if (tv[1] > tv[0]) { float fv = tv[0]; tv[0] = tv[1]; tv[1] = fv; int iv = ti[0]; ti[0] = ti[1]; ti[1] = iv; }
            }
        }
    }

    float mx = tv[0];
    float e0 = expf(tv[0] - mx), e1 = expf(tv[1] - mx),
          e2 = expf(tv[2] - mx), e3 = expf(tv[3] - mx);
    float inv = 1.0f / (4.0f * (e0 + e1 + e2 + e3));

    int base = (r * NH + h) * NP;
    float ee[4] = {e0, e1, e2, e3};
#pragma unroll
    for (int p = 0; p < 4; p++) {
        g_attw[base + p] = ee[p] * inv;
        g_offs[(size_t)(base + p) * 2 + 0] = (float)(ti[p] % 7 - 3);
        g_offs[(size_t)(base + p) * 2 + 1] = (float)(ti[p] / 7 - 3);
    }
}

// =====================================================================
// Deformable sampling, warp-specialized. Output tf32-rounded (feeds
// the Wo tf32 GEMM which then skips per-fragment cvt).
// =====================================================================
__global__ void __launch_bounds__(256)
sample_kernel(const float* __restrict__ ref)
{
    __shared__ float s_w[8][16][4];
    __shared__ int   s_i[8][16][4];

    int r = blockIdx.x;
    int wid = threadIdx.x >> 5, lane = threadIdx.x & 31;
    int b = r / LEN;

    if (lane < 16) {
        const int HsA[4] = {92, 46, 23, 12};
        const int S0A[4] = {0, 8464, 10580, 11109};
        int l = lane >> 2, p = lane & 3;
        int Wi = HsA[l];
        float Wf = (float)Wi;

        float rx = ref[(size_t)(r * NL + l) * 2 + 0];
        float ry = ref[(size_t)(r * NL + l) * 2 + 1];
        int base = (r * NH + wid) * NP + p;
        float wgt = g_attw[base];
        float ox  = g_offs[(size_t)base * 2 + 0];
        float oy  = g_offs[(size_t)base * 2 + 1];

        float locx = rx + ox / Wf;
        float locy = ry + oy / Wf;
        float xf = locx * Wf - 0.5f;
        float yf = locy * Wf - 0.5f;
        float x0f = floorf(xf), y0f = floorf(yf);
        float tx = xf - x0f, ty = yf - y0f;
        int x0 = (int)x0f, y0 = (int)y0f;
        int x1 = x0 + 1,  y1 = y0 + 1;

        float w00 = (1.0f - tx) * (1.0f - ty) * wgt;
        float w01 = tx * (1.0f - ty) * wgt;
        float w10 = (1.0f - tx) * ty * wgt;
        float w11 = tx * ty * wgt;

        bool vx0 = (x0 >= 0) & (x0 < Wi);
        bool vx1 = (x1 >= 0) & (x1 < Wi);
        bool vy0 = (y0 >= 0) & (y0 < Wi);
        bool vy1 = (y1 >= 0) & (y1 < Wi);

        int x0c = min(max(x0, 0), Wi - 1), x1c = min(max(x1, 0), Wi - 1);
        int y0c = min(max(y0, 0), Wi - 1), y1c = min(max(y1, 0), Wi - 1);
        int rb = b * LEN + S0A[l];

        s_w[wid][lane][0] = (vy0 & vx0) ? w00 : 0.0f;
        s_w[wid][lane][1] = (vy0 & vx1) ? w01 : 0.0f;
        s_w[wid][lane][2] = (vy1 & vx0) ? w10 : 0.0f;
        s_w[wid][lane][3] = (vy1 & vx1) ? w11 : 0.0f;
        s_i[wid][lane][0] = rb + y0c * Wi + x0c;
        s_i[wid][lane][1] = rb + y0c * Wi + x1c;
        s_i[wid][lane][2] = rb + y1c * Wi + x0c;
        s_i[wid][lane][3] = rb + y1c * Wi + x1c;
    }
    __syncwarp();

    const float* vb = g_value + wid * DH + lane;
    float acc = 0.0f;
#pragma unroll
    for (int c = 0; c < 16; c++) {
        float4 w  = *(const float4*)s_w[wid][c];
        int4   ii = *(const int4*)s_i[wid][c];
        acc = fmaf(w.x, vb[(size_t)ii.x * D], acc);
        acc = fmaf(w.y, vb[(size_t)ii.y * D], acc);
        acc = fmaf(w.z, vb[(size_t)ii.z * D], acc);
        acc = fmaf(w.w, vb[(size_t)ii.w * D], acc);
    }
    g_attnout[(size_t)r * D + wid * DH + lane] = __uint_as_float(f2tf32(acc));
}

// =====================================================================
// out = LayerNorm(a + res) * g + b; optionally also write tf32 copy
// =====================================================================
template<int WR>
__global__ void add_ln_kernel(const float* __restrict__ a, const float* __restrict__ res,
                              const float* __restrict__ gg, const float* __restrict__ bb,
                              float* __restrict__ out, float* __restrict__ out_r)
{
    int row = blockIdx.x;
    int t = threadIdx.x;
    float v = a[(size_t)row * D + t] + res[(size_t)row * D + t];

    __shared__ float s1[8], s2[8];
    float s = v, u = v * v;
#pragma unroll
    for (int o = 16; o; o >>= 1) {
        s += __shfl_xor_sync(0xffffffffu, s, o);
        u += __shfl_xor_sync(0xffffffffu, u, o);
    }
    if ((t & 31) == 0) { s1[t >> 5] = s; s2[t >> 5] = u; }
    __syncthreads();
    float sum = 0.f, sq = 0.f;
#pragma unroll
    for (int i = 0; i < 8; i++) { sum += s1[i]; sq += s2[i]; }
    float mean = sum * (1.0f / D);
    float var  = sq * (1.0f / D) - mean * mean;
    float rs = rsqrtf(var + 1e-5f);
    float o = (v - mean) * rs * gg[t] + bb[t];
    out[(size_t)row * D + t] = o;
    if (WR) out_r[(size_t)row * D + t] = __uint_as_float(f2tf32(o));
}

// =====================================================================
extern "C" void kernel_launch(void* const* d_in, const int* in_sizes, int n_in,
                              void* d_out, int out_size)
{
    const float* src  = (const float*)d_in[0];
    const float* ref  = (const float*)d_in[2];
    const float* m0   = (const float*)d_in[4];
    const float* m1   = (const float*)d_in[5];
    const float* m2   = (const float*)d_in[6];
    const float* m3   = (const float*)d_in[7];
    const float* pmw  = (const float*)d_in[10];
    const float* pmb  = (const float*)d_in[11];
    const float* Wv   = (const float*)d_in[12];
    const float* bv   = (const float*)d_in[13];
    const float* Wo   = (const float*)d_in[14];
    const float* bo   = (const float*)d_in[15];
    const float* ln1g = (const float*)d_in[16];
    const float* ln1b = (const float*)d_in[17];
    const float* W1   = (const float*)d_in[18];
    const float* b1   = (const float*)d_in[19];
    const float* W2   = (const float*)d_in[20];
    const float* b2   = (const float*)d_in[21];
    const float* ln2g = (const float*)d_in[22];
    const float* ln2b = (const float*)d_in[23];
    float* out = (float*)d_out;

    float *pv, *pao, *ptmp, *px, *pxr, *ph, *pWvT, *pWoT, *pW1T, *pW2T;
    cudaGetSymbolAddress((void**)&pv,   g_value);
    cudaGetSymbolAddress((void**)&pao,  g_attnout);
    cudaGetSymbolAddress((void**)&ptmp, g_tmp);
    cudaGetSymbolAddress((void**)&px,   g_x);
    cudaGetSymbolAddress((void**)&pxr,  g_xr);
    cudaGetSymbolAddress((void**)&ph,   g_hid);
    cudaGetSymbolAddress((void**)&pWvT, g_WvT);
    cudaGetSymbolAddress((void**)&pWoT, g_WoT);
    cudaGetSymbolAddress((void**)&pW1T, g_W1T);
    cudaGetSymbolAddress((void**)&pW2T, g_W2T);

    cudaFuncSetAttribute((const void*)gemm_tc<0,1,0>, cudaFuncAttributeMaxDynamicSharedMemorySize, GEMM_SMEM);
    cudaFuncSetAttribute((const void*)gemm_tc<0,0,0>, cudaFuncAttributeMaxDynamicSharedMemorySize, GEMM_SMEM);
    cudaFuncSetAttribute((const void*)gemm_tc<1,0,1>, cudaFuncAttributeMaxDynamicSharedMemorySize, GEMM_SMEM);

    const int MB = (MROWS + 127) / 128;   // 176

    // 0. all weight transposes + tf32 rounding (B^T, K-major), one launch
    transpose_all_kernel<<<dim3(32, 32, 4), dim3(32, 8)>>>(Wv, Wo, W1, W2,
                                                           pWvT, pWoT, pW1T, pW2T);

    // 1. top-k offsets + attention weights
    topk_kernel<<<(MROWS * NH + 255) / 256, 256>>>(m0, m1, m2, m3, pmw, pmb);

    // 2. value = src @ Wv + bv          (A=src raw -> cvt at load)
    gemm_tc<0,1,0><<<dim3(2, MB), 128, GEMM_SMEM>>>(src, pWvT, bv, pv, MROWS, 256, 256);

    // 3. deformable bilinear sampling -> attnout (tf32-rounded)
    sample_kernel<<<MROWS, 256>>>(ref);

    // 4. attn_out = attnout @ Wo + bo   (A pre-rounded)
    gemm_tc<0,0,0><<<dim3(2, MB), 128, GEMM_SMEM>>>(pao, pWoT, bo, ptmp, MROWS, 256, 256);

    // 5. x = LN(src + attn_out); also tf32 copy for W1 GEMM
    add_ln_kernel<1><<<MROWS, 256>>>(ptmp, src, ln1g, ln1b, px, pxr);

    // 6. hid = relu(x @ W1 + b1)        (A pre-rounded; out rounded for W2)
    gemm_tc<1,0,1><<<dim3(8, MB), 128, GEMM_SMEM>>>(pxr, pW1T, b1, ph, MROWS, 1024, 256);

    // 7. y = hid @ W2 + b2              (A pre-rounded)
    gemm_tc<0,0,0><<<dim3(2, MB), 128, GEMM_SMEM>>>(ph, pW2T, b2, ptmp, MROWS, 256, 1024);

    // 8. out = LN(x + y)
    add_ln_kernel<0><<<MROWS, 256>>>(ptmp, px, ln2g, ln2b, out, nullptr);
}

// round 7
// speedup vs baseline: 3.9223x; 1.2604x over previous
#include <cuda_runtime.h>
#include <cuda_bf16.h>
#include <cstdint>
#include <math.h>

#define BS   2
#define LEN  11253
#define MROWS (BS*LEN)   // 22506
#define D    256
#define NH   8
#define NP   4
#define NL   4
#define DH   32
#define DFF  1024

// ---- scratch (device globals; no allocation allowed) ----
__device__ float          g_value  [(size_t)MROWS * D];
__device__ __nv_bfloat16  g_srcb   [(size_t)MROWS * D];
__device__ __nv_bfloat16  g_attnb  [(size_t)MROWS * D];
__device__ float          g_tmp    [(size_t)MROWS * D];
__device__ float          g_x      [(size_t)MROWS * D];
__device__ __nv_bfloat16  g_xr     [(size_t)MROWS * D];
__device__ __nv_bfloat16  g_hid    [(size_t)MROWS * DFF];
__device__ float          g_attw   [(size_t)MROWS * NH * NP];
__device__ float          g_offs   [(size_t)MROWS * NH * NP * 2];
__device__ __nv_bfloat16  g_WvT    [D * D];
__device__ __nv_bfloat16  g_WoT    [D * D];
__device__ __nv_bfloat16  g_W1T    [DFF * D];
__device__ __nv_bfloat16  g_W2T    [D * DFF];

// =====================================================================
// helpers
// =====================================================================
__device__ __forceinline__ void mma_bf16(float* d, const uint32_t* a, const uint32_t* b) {
    asm volatile(
        "mma.sync.aligned.m16n8k16.row.col.f32.bf16.bf16.f32 "
        "{%0,%1,%2,%3}, {%4,%5,%6,%7}, {%8,%9}, {%0,%1,%2,%3};"
        : "+f"(d[0]), "+f"(d[1]), "+f"(d[2]), "+f"(d[3])
        : "r"(a[0]), "r"(a[1]), "r"(a[2]), "r"(a[3]), "r"(b[0]), "r"(b[1]));
}

// =====================================================================
// BF16 tensor-core GEMM: C[M,N] = A[M,K] @ BT[N,K]^T + bias (opt relu)
// 128x128 CTA tile, BK=32, 3-stage cp.async, 4 warps (2x2), 64x64/warp.
// Smem rows stride 40 bf16 (80B): fragment LDS conflict-free
// (word bank = (20g + qc) mod 32, bijective over the warp).
// OUTBF16: store C as bf16 (consumer is another bf16 GEMM).
// =====================================================================
#define SSTR        40                    // bf16 units per smem row
#define TILE_B      (128*SSTR*2)          // 10240 bytes per operand tile
#define STAGE_B     (2*TILE_B)            // 20480
#define GEMM_SMEM   (3*STAGE_B)           // 61440

template<int RELU, int OUTBF16>
__global__ void __launch_bounds__(128, 2)
gemm_bf(const __nv_bfloat16* __restrict__ A, const __nv_bfloat16* __restrict__ BT,
        const float* __restrict__ bias, void* __restrict__ Cv,
        int M, int N, int K)
{
    extern __shared__ __align__(16) char smem[];
    int tid = threadIdx.x, wid = tid >> 5, lane = tid & 31;
    int g = lane >> 2, qc = lane & 3;
    int row0 = blockIdx.y * 128, col0 = blockIdx.x * 128;
    int wm = (wid & 1) * 64, wn = (wid >> 1) * 64;

    const int NC = K >> 5;

    auto load_chunk = [&](int c) {
        if (c >= NC) { asm volatile("cp.async.commit_group;"); return; }
        char* As = smem + (c % 3) * STAGE_B;
        char* Bs = As + TILE_B;
        int k0 = c * 32;
        const __nv_bfloat16* Ab = A + (size_t)row0 * K + k0;
        const __nv_bfloat16* Bb = BT + (size_t)col0 * K + k0;
        uint32_t a_st, b_st;
        asm("{ .reg .u64 t; cvta.to.shared.u64 t, %1; cvt.u32.u64 %0, t; }" : "=r"(a_st) : "l"(As));
        asm("{ .reg .u64 t; cvta.to.shared.u64 t, %1; cvt.u32.u64 %0, t; }" : "=r"(b_st) : "l"(Bs));
#pragma unroll
        for (int i = 0; i < 4; i++) {
            int f4 = tid + i * 128;           // 512 16B-segments per tile
            int r = f4 >> 2, seg = f4 & 3;
            uint32_t off = (uint32_t)(r * (SSTR * 2) + seg * 16);
            uint32_t nbytes = (row0 + r < M) ? 16u : 0u;
            asm volatile("cp.async.cg.shared.global [%0], [%1], 16, %2;"
                :: "r"(a_st + off), "l"(Ab + (size_t)r * K + seg * 8), "r"(nbytes));
            asm volatile("cp.async.cg.shared.global [%0], [%1], 16;"
                :: "r"(b_st + off), "l"(Bb + (size_t)r * K + seg * 8));
        }
        asm volatile("cp.async.commit_group;");
    };

    float acc[4][8][4];
#pragma unroll
    for (int mt = 0; mt < 4; mt++)
#pragma unroll
        for (int nt = 0; nt < 8; nt++)
#pragma unroll
            for (int i = 0; i < 4; i++) acc[mt][nt][i] = 0.0f;

    load_chunk(0);
    load_chunk(1);

    for (int c = 0; c < NC; c++) {
        asm volatile("cp.async.wait_group 1;");
        __syncthreads();
        load_chunk(c + 2);

        const uint32_t* AsW = (const uint32_t*)(smem + (c % 3) * STAGE_B);
        const uint32_t* BsW = (const uint32_t*)(smem + (c % 3) * STAGE_B + TILE_B);
#pragma unroll
        for (int ks = 0; ks < 2; ks++) {
            int kw = ks * 8;                 // word offset of kstep within tile row
            uint32_t af[4][4];
#pragma unroll
            for (int mt = 0; mt < 4; mt++) {
                int r = wm + mt * 16 + g;
                af[mt][0] = AsW[r * 20 + kw + qc];
                af[mt][1] = AsW[(r + 8) * 20 + kw + qc];
                af[mt][2] = AsW[r * 20 + kw + qc + 4];
                af[mt][3] = AsW[(r + 8) * 20 + kw + qc + 4];
            }
            uint32_t bf[8][2];
#pragma unroll
            for (int nt = 0; nt < 8; nt++) {
                int n = wn + nt * 8 + g;
                bf[nt][0] = BsW[n * 20 + kw + qc];
                bf[nt][1] = BsW[n * 20 + kw + qc + 4];
            }
#pragma unroll
            for (int mt = 0; mt < 4; mt++)
#pragma unroll
                for (int nt = 0; nt < 8; nt++)
                    mma_bf16(acc[mt][nt], af[mt], bf[nt]);
        }
    }

    // epilogue
#pragma unroll
    for (int mt = 0; mt < 4; mt++) {
        int r0 = row0 + wm + mt * 16 + g;
#pragma unroll
        for (int nt = 0; nt < 8; nt++) {
            int col = col0 + wn + nt * 8 + 2 * qc;
            float b0 = bias[col], b1 = bias[col + 1];
#pragma unroll
            for (int half = 0; half < 2; half++) {
                int rr = r0 + half * 8;
                if (rr < M) {
                    float vx = acc[mt][nt][half * 2 + 0] + b0;
                    float vy = acc[mt][nt][half * 2 + 1] + b1;
                    if (RELU) { vx = fmaxf(vx, 0.f); vy = fmaxf(vy, 0.f); }
                    if (OUTBF16) {
                        __nv_bfloat162 v2 = __floats2bfloat162_rn(vx, vy);
                        *(__nv_bfloat162*)((__nv_bfloat16*)Cv + (size_t)rr * N + col) = v2;
                    } else {
                        *(float2*)((float*)Cv + (size_t)rr * N + col) = make_float2(vx, vy);
                    }
                }
            }
        }
    }
}

// =====================================================================
// Fused transposes of all 4 weight matrices -> bf16, K-major.
// =====================================================================
__global__ void transpose_all_kernel(const float* __restrict__ Wv, const float* __restrict__ Wo,
                                     const float* __restrict__ W1, const float* __restrict__ W2,
                                     __nv_bfloat16* __restrict__ WvT, __nv_bfloat16* __restrict__ WoT,
                                     __nv_bfloat16* __restrict__ W1T, __nv_bfloat16* __restrict__ W2T)
{
    __shared__ float t[32][33];
    int z = blockIdx.z;
    const float* src; __nv_bfloat16* dst; int R, C;
    if (z == 0)      { src = Wv; dst = WvT; R = 256;  C = 256;  }
    else if (z == 1) { src = Wo; dst = WoT; R = 256;  C = 256;  }
    else if (z == 2) { src = W1; dst = W1T; R = 256;  C = 1024; }
    else             { src = W2; dst = W2T; R = 1024; C = 256;  }

    int bx = blockIdx.x * 32, by = blockIdx.y * 32;
    if (bx >= C || by >= R) return;
#pragma unroll
    for (int i = 0; i < 32; i += 8) {
        int r = by + threadIdx.y + i, c = bx + threadIdx.x;
        if (r < R && c < C) t[threadIdx.y + i][threadIdx.x] = src[(size_t)r * C + c];
    }
    __syncthreads();
#pragma unroll
    for (int i = 0; i < 32; i += 8) {
        int r = bx + threadIdx.y + i, c = by + threadIdx.x;
        if (r < C && c < R) dst[(size_t)r * R + c] = __float2bfloat16(t[threadIdx.x][threadIdx.y + i]);
    }
}

// =====================================================================
// fp32 -> bf16 bulk convert (for src)
// =====================================================================
__global__ void f2bf_kernel(const float4* __restrict__ in, __nv_bfloat162* __restrict__ out, int n4)
{
    int i = blockIdx.x * blockDim.x + threadIdx.x;
    if (i < n4) {
        float4 v = in[i];
        out[2 * i + 0] = __floats2bfloat162_rn(v.x, v.y);
        out[2 * i + 1] = __floats2bfloat162_rn(v.z, v.w);
    }
}

// =====================================================================
// Top-4 over 7x7 window of (w*mask + b), pad=0, stable ties (lower idx).
// =====================================================================
__global__ void topk_kernel(const float* __restrict__ m0, const float* __restrict__ m1,
                            const float* __restrict__ m2, const float* __restrict__ m3,
                            const float* __restrict__ pmw, const float* __restrict__ pmb)
{
    int t = blockIdx.x * blockDim.x + threadIdx.x;
    if (t >= MROWS * NH) return;
    int h = t % NH;
    int r = t / NH;
    int q = r % LEN;
    int b = r / LEN;

    int l, Wl, s0;
    const float* mk;
    if (q < 8464)        { l = 0; Wl = 92; s0 = 0;     mk = m0; }
    else if (q < 10580)  { l = 1; Wl = 46; s0 = 8464;  mk = m1; }
    else if (q < 11109)  { l = 2; Wl = 23; s0 = 10580; mk = m2; }
    else                 { l = 3; Wl = 12; s0 = 11109; mk = m3; }
    int Hl = Wl;
    int pos = q - s0;
    int y = pos / Wl, x = pos % Wl;

    float w  = pmw[l * NH + h];
    float bb = pmb[l * NH + h];
    const float* mb = mk + (size_t)b * Hl * Wl;

    float tv[4] = {-1e30f, -1e30f, -1e30f, -1e30f};
    int   ti[4] = {0, 0, 0, 0};

    for (int i = 0; i < 7; i++) {
        int yy = y + i - 3;
        for (int j = 0; j < 7; j++) {
            int xx = x + j - 3;
            float val = 0.0f;
            if (yy >= 0 && yy < Hl && xx >= 0 && xx < Wl)
                val = fmaf(mb[yy * Wl + xx], w, bb);
            if (val > tv[3]) {
                int k = i * 7 + j;
                tv[3] = val; ti[3] = k;
                if (tv[3] > tv[2]) { float fv = tv[2]; tv[2] = tv[3]; tv[3] = fv; int iv = ti[2]; ti[2] = ti[3]; ti[3] = iv; }
                if (tv[2] > tv[1]) { float fv = tv[1]; tv[1] = tv[2]; tv[2] = fv; int iv = ti[1]; ti[1] = ti[2]; ti[2] = iv; }
                if (tv[1] > tv[0]) { float fv = tv[0]; tv[0] = tv[1]; tv[1] = fv; int iv = ti[0]; ti[0] = ti[1]; ti[1] = iv; }
            }
        }
    }

    float mx = tv[0];
    float e0 = expf(tv[0] - mx), e1 = expf(tv[1] - mx),
          e2 = expf(tv[2] - mx), e3 = expf(tv[3] - mx);
    float inv = 1.0f / (4.0f * (e0 + e1 + e2 + e3));

    int base = (r * NH + h) * NP;
    float ee[4] = {e0, e1, e2, e3};
#pragma unroll
    for (int p = 0; p < 4; p++) {
        g_attw[base + p] = ee[p] * inv;
        g_offs[(size_t)(base + p) * 2 + 0] = (float)(ti[p] % 7 - 3);
        g_offs[(size_t)(base + p) * 2 + 1] = (float)(ti[p] / 7 - 3);
    }
}

// =====================================================================
// Deformable sampling (fp32 math) -> bf16 output for Wo GEMM.
// =====================================================================
__global__ void __launch_bounds__(256)
sample_kernel(const float* __restrict__ ref)
{
    __shared__ float s_w[8][16][4];
    __shared__ int   s_i[8][16][4];

    int r = blockIdx.x;
    int wid = threadIdx.x >> 5, lane = threadIdx.x & 31;
    int b = r / LEN;

    if (lane < 16) {
        const int HsA[4] = {92, 46, 23, 12};
        const int S0A[4] = {0, 8464, 10580, 11109};
        int l = lane >> 2, p = lane & 3;
        int Wi = HsA[l];
        float Wf = (float)Wi;

        float rx = ref[(size_t)(r * NL + l) * 2 + 0];
        float ry = ref[(size_t)(r * NL + l) * 2 + 1];
        int base = (r * NH + wid) * NP + p;
        float wgt = g_attw[base];
        float ox  = g_offs[(size_t)base * 2 + 0];
        float oy  = g_offs[(size_t)base * 2 + 1];

        float locx = rx + ox / Wf;
        float locy = ry + oy / Wf;
        float xf = locx * Wf - 0.5f;
        float yf = locy * Wf - 0.5f;
        float x0f = floorf(xf), y0f = floorf(yf);
        float tx = xf - x0f, ty = yf - y0f;
        int x0 = (int)x0f, y0 = (int)y0f;
        int x1 = x0 + 1,  y1 = y0 + 1;

        float w00 = (1.0f - tx) * (1.0f - ty) * wgt;
        float w01 = tx * (1.0f - ty) * wgt;
        float w10 = (1.0f - tx) * ty * wgt;
        float w11 = tx * ty * wgt;

        bool vx0 = (x0 >= 0) & (x0 < Wi);
        bool vx1 = (x1 >= 0) & (x1 < Wi);
        bool vy0 = (y0 >= 0) & (y0 < Wi);
        bool vy1 = (y1 >= 0) & (y1 < Wi);

        int x0c = min(max(x0, 0), Wi - 1), x1c = min(max(x1, 0), Wi - 1);
        int y0c = min(max(y0, 0), Wi - 1), y1c = min(max(y1, 0), Wi - 1);
        int rb = b * LEN + S0A[l];

        s_w[wid][lane][0] = (vy0 & vx0) ? w00 : 0.0f;
        s_w[wid][lane][1] = (vy0 & vx1) ? w01 : 0.0f;
        s_w[wid][lane][2] = (vy1 & vx0) ? w10 : 0.0f;
        s_w[wid][lane][3] = (vy1 & vx1) ? w11 : 0.0f;
        s_i[wid][lane][0] = rb + y0c * Wi + x0c;
        s_i[wid][lane][1] = rb + y0c * Wi + x1c;
        s_i[wid][lane][2] = rb + y1c * Wi + x0c;
        s_i[wid][lane][3] = rb + y1c * Wi + x1c;
    }
    __syncwarp();

    const float* vb = g_value + wid * DH + lane;
    float acc = 0.0f;
#pragma unroll
    for (int c = 0; c < 16; c++) {
        float4 w  = *(const float4*)s_w[wid][c];
        int4   ii = *(const int4*)s_i[wid][c];
        acc = fmaf(w.x, vb[(size_t)ii.x * D], acc);
        acc = fmaf(w.y, vb[(size_t)ii.y * D], acc);
        acc = fmaf(w.z, vb[(size_t)ii.z * D], acc);
        acc = fmaf(w.w, vb[(size_t)ii.w * D], acc);
    }
    g_attnb[(size_t)r * D + wid * DH + lane] = __float2bfloat16(acc);
}

// =====================================================================
// out = LayerNorm(a + res) * g + b; optionally also write bf16 copy
// =====================================================================
template<int WR>
__global__ void add_ln_kernel(const float* __restrict__ a, const float* __restrict__ res,
                              const float* __restrict__ gg, const float* __restrict__ bb,
                              float* __restrict__ out, __nv_bfloat16* __restrict__ out_r)
{
    int row = blockIdx.x;
    int t = threadIdx.x;
    float v = a[(size_t)row * D + t] + res[(size_t)row * D + t];

    __shared__ float s1[8], s2[8];
    float s = v, u = v * v;
#pragma unroll
    for (int o = 16; o; o >>= 1) {
        s += __shfl_xor_sync(0xffffffffu, s, o);
        u += __shfl_xor_sync(0xffffffffu, u, o);
    }
    if ((t & 31) == 0) { s1[t >> 5] = s; s2[t >> 5] = u; }
    __syncthreads();
    float sum = 0.f, sq = 0.f;
#pragma unroll
    for (int i = 0; i < 8; i++) { sum += s1[i]; sq += s2[i]; }
    float mean = sum * (1.0f / D);
    float var  = sq * (1.0f / D) - mean * mean;
    float rs = rsqrtf(var + 1e-5f);
    float o = (v - mean) * rs * gg[t] + bb[t];
    out[(size_t)row * D + t] = o;
    if (WR) out_r[(size_t)row * D + t] = __float2bfloat16(o);
}

// =====================================================================
extern "C" void kernel_launch(void* const* d_in, const int* in_sizes, int n_in,
                              void* d_out, int out_size)
{
    const float* src  = (const float*)d_in[0];
    const float* ref  = (const float*)d_in[2];
    const float* m0   = (const float*)d_in[4];
    const float* m1   = (const float*)d_in[5];
    const float* m2   = (const float*)d_in[6];
    const float* m3   = (const float*)d_in[7];
    const float* pmw  = (const float*)d_in[10];
    const float* pmb  = (const float*)d_in[11];
    const float* Wv   = (const float*)d_in[12];
    const float* bv   = (const float*)d_in[13];
    const float* Wo   = (const float*)d_in[14];
    const float* bo   = (const float*)d_in[15];
    const float* ln1g = (const float*)d_in[16];
    const float* ln1b = (const float*)d_in[17];
    const float* W1   = (const float*)d_in[18];
    const float* b1   = (const float*)d_in[19];
    const float* W2   = (const float*)d_in[20];
    const float* b2   = (const float*)d_in[21];
    const float* ln2g = (const float*)d_in[22];
    const float* ln2b = (const float*)d_in[23];
    float* out = (float*)d_out;

    float *pv, *ptmp, *px;
    __nv_bfloat16 *psb, *pab, *pxr, *ph, *pWvT, *pWoT, *pW1T, *pW2T;
    cudaGetSymbolAddress((void**)&pv,   g_value);
    cudaGetSymbolAddress((void**)&psb,  g_srcb);
    cudaGetSymbolAddress((void**)&pab,  g_attnb);
    cudaGetSymbolAddress((void**)&ptmp, g_tmp);
    cudaGetSymbolAddress((void**)&px,   g_x);
    cudaGetSymbolAddress((void**)&pxr,  g_xr);
    cudaGetSymbolAddress((void**)&ph,   g_hid);
    cudaGetSymbolAddress((void**)&pWvT, g_WvT);
    cudaGetSymbolAddress((void**)&pWoT, g_WoT);
    cudaGetSymbolAddress((void**)&pW1T, g_W1T);
    cudaGetSymbolAddress((void**)&pW2T, g_W2T);

    cudaFuncSetAttribute((const void*)gemm_bf<0,0>, cudaFuncAttributeMaxDynamicSharedMemorySize, GEMM_SMEM);
    cudaFuncSetAttribute((const void*)gemm_bf<1,1>, cudaFuncAttributeMaxDynamicSharedMemorySize, GEMM_SMEM);

    const int MB = (MROWS + 127) / 128;   // 176

    // 0. weight transposes -> bf16 (one launch) + src -> bf16
    transpose_all_kernel<<<dim3(32, 32, 4), dim3(32, 8)>>>(Wv, Wo, W1, W2,
                                                           pWvT, pWoT, pW1T, pW2T);
    {
        int n4 = MROWS * D / 4;
        f2bf_kernel<<<(n4 + 255) / 256, 256>>>((const float4*)src, (__nv_bfloat162*)psb, n4);
    }

    // 1. top-k offsets + attention weights
    topk_kernel<<<(MROWS * NH + 255) / 256, 256>>>(m0, m1, m2, m3, pmw, pmb);

    // 2. value = src @ Wv + bv  (fp32 out for sampler)
    gemm_bf<0,0><<<dim3(2, MB), 128, GEMM_SMEM>>>(psb, pWvT, bv, pv, MROWS, 256, 256);

    // 3. deformable bilinear sampling -> bf16 attnout
    sample_kernel<<<MROWS, 256>>>(ref);

    // 4. attn_out = attnout @ Wo + bo  (fp32 out)
    gemm_bf<0,0><<<dim3(2, MB), 128, GEMM_SMEM>>>(pab, pWoT, bo, ptmp, MROWS, 256, 256);

    // 5. x = LN(src + attn_out); fp32 x + bf16 copy
    add_ln_kernel<1><<<MROWS, 256>>>(ptmp, src, ln1g, ln1b, px, pxr);

    // 6. hid = relu(x @ W1 + b1) -> bf16
    gemm_bf<1,1><<<dim3(8, MB), 128, GEMM_SMEM>>>(pxr, pW1T, b1, ph, MROWS, 1024, 256);

    // 7. y = hid @ W2 + b2  (fp32 out)
    gemm_bf<0,0><<<dim3(2, MB), 128, GEMM_SMEM>>>(ph, pW2T, b2, ptmp, MROWS, 256, 1024);

    // 8. out = LN(x + y)
    add_ln_kernel<0><<<MROWS, 256>>>(ptmp, px, ln2g, ln2b, out, nullptr);
}

// round 8
// speedup vs baseline: 4.3164x; 1.1005x over previous
#include <cuda_runtime.h>
#include <cuda_bf16.h>
#include <cstdint>
#include <math.h>

#define BS   2
#define LEN  11253
#define MROWS (BS*LEN)   // 22506
#define D    256
#define NH   8
#define NP   4
#define NL   4
#define DH   32
#define DFF  1024

// ---- scratch (device globals; no allocation allowed) ----
__device__ float          g_value  [(size_t)MROWS * D];
__device__ __nv_bfloat16  g_srcb   [(size_t)MROWS * D];
__device__ __nv_bfloat16  g_attnb  [(size_t)MROWS * D];
__device__ float          g_tmp    [(size_t)MROWS * D];
__device__ float          g_x      [(size_t)MROWS * D];
__device__ __nv_bfloat16  g_xr     [(size_t)MROWS * D];
__device__ __nv_bfloat16  g_hid    [(size_t)MROWS * DFF];
__device__ float          g_attw   [(size_t)MROWS * NH * NP];
__device__ float          g_offs   [(size_t)MROWS * NH * NP * 2];
__device__ __nv_bfloat16  g_WvT    [D * D];
__device__ __nv_bfloat16  g_WoT    [D * D];
__device__ __nv_bfloat16  g_W1T    [DFF * D];
__device__ __nv_bfloat16  g_W2T    [D * DFF];

// =====================================================================
// helpers
// =====================================================================
__device__ __forceinline__ void mma_bf16(float* d, const uint32_t* a, const uint32_t* b) {
    asm volatile(
        "mma.sync.aligned.m16n8k16.row.col.f32.bf16.bf16.f32 "
        "{%0,%1,%2,%3}, {%4,%5,%6,%7}, {%8,%9}, {%0,%1,%2,%3};"
        : "+f"(d[0]), "+f"(d[1]), "+f"(d[2]), "+f"(d[3])
        : "r"(a[0]), "r"(a[1]), "r"(a[2]), "r"(a[3]), "r"(b[0]), "r"(b[1]));
}
__device__ __forceinline__ void ldsm_x4(uint32_t* r, uint32_t addr) {
    asm volatile("ldmatrix.sync.aligned.m8n8.x4.shared.b16 {%0,%1,%2,%3}, [%4];"
        : "=r"(r[0]), "=r"(r[1]), "=r"(r[2]), "=r"(r[3]) : "r"(addr));
}

// =====================================================================
// BF16 tensor-core GEMM: C[M,N] = A[M,K] @ BT[N,K]^T + bias (opt relu)
// 128x128 CTA tile, BK=32, 3-stage cp.async, 8 warps (2m x 4n),
// 64x32 warp tile, ldmatrix fragment loads, 2 CTAs/SM.
// Smem rows stride 40 bf16 (80B): LDSM rows hit all 32 banks once.
// =====================================================================
#define SSTR        40                    // bf16 units per smem row
#define TILE_B      (128*SSTR*2)          // 10240 bytes per operand tile
#define STAGE_B     (2*TILE_B)            // 20480
#define GEMM_SMEM   (3*STAGE_B)           // 61440

template<int RELU, int OUTBF16>
__global__ void __launch_bounds__(256, 2)
gemm_bf(const __nv_bfloat16* __restrict__ A, const __nv_bfloat16* __restrict__ BT,
        const float* __restrict__ bias, void* __restrict__ Cv,
        int M, int N, int K)
{
    extern __shared__ __align__(16) char smem[];
    int tid = threadIdx.x, wid = tid >> 5, lane = tid & 31;
    int g = lane >> 2, qc = lane & 3;
    int row0 = blockIdx.y * 128, col0 = blockIdx.x * 128;
    int wm = (wid & 1) * 64, wn = (wid >> 1) * 32;

    uint32_t smem_u;
    asm("{ .reg .u64 t; cvta.to.shared.u64 t, %1; cvt.u32.u64 %0, t; }" : "=r"(smem_u) : "l"(smem));

    const int NC = K >> 5;

    auto load_chunk = [&](int c) {
        if (c >= NC) { asm volatile("cp.async.commit_group;"); return; }
        uint32_t a_st = smem_u + (c % 3) * STAGE_B;
        uint32_t b_st = a_st + TILE_B;
        int k0 = c * 32;
        const __nv_bfloat16* Ab = A + (size_t)row0 * K + k0;
        const __nv_bfloat16* Bb = BT + (size_t)col0 * K + k0;
#pragma unroll
        for (int i = 0; i < 2; i++) {
            int f4 = tid + i * 256;           // 512 16B-segments per tile
            int r = f4 >> 2, seg = f4 & 3;
            uint32_t off = (uint32_t)(r * (SSTR * 2) + seg * 16);
            uint32_t nbytes = (row0 + r < M) ? 16u : 0u;
            asm volatile("cp.async.cg.shared.global [%0], [%1], 16, %2;"
                :: "r"(a_st + off), "l"(Ab + (size_t)r * K + seg * 8), "r"(nbytes));
            asm volatile("cp.async.cg.shared.global [%0], [%1], 16;"
                :: "r"(b_st + off), "l"(Bb + (size_t)r * K + seg * 8));
        }
        asm volatile("cp.async.commit_group;");
    };

    float acc[4][4][4];
#pragma unroll
    for (int mt = 0; mt < 4; mt++)
#pragma unroll
        for (int nt = 0; nt < 4; nt++)
#pragma unroll
            for (int i = 0; i < 4; i++) acc[mt][nt][i] = 0.0f;

    // ldmatrix lane addressing (within-tile, bytes)
    int sub = lane >> 3, rr = lane & 7;
    // A: matrices [m0-7 k0-7][m8-15 k0-7][m0-7 k8-15][m8-15 k8-15]
    uint32_t a_lrow = (uint32_t)(wm + (sub & 1) * 8 + rr);
    uint32_t a_koff = (uint32_t)((sub >> 1) * 16);
    // B: matrices [n0-7 k0-7][n0-7 k8-15][n8-15 k0-7][n8-15 k8-15]
    uint32_t b_lrow = (uint32_t)(wn + (sub >> 1) * 8 + rr);
    uint32_t b_koff = (uint32_t)((sub & 1) * 16);

    load_chunk(0);
    load_chunk(1);

    for (int c = 0; c < NC; c++) {
        asm volatile("cp.async.wait_group 1;");
        __syncthreads();
        load_chunk(c + 2);

        uint32_t a_base = smem_u + (c % 3) * STAGE_B;
        uint32_t b_base = a_base + TILE_B;
#pragma unroll
        for (int ks = 0; ks < 2; ks++) {
            uint32_t kb = (uint32_t)(ks * 32);
            uint32_t af[4][4];
#pragma unroll
            for (int mt = 0; mt < 4; mt++)
                ldsm_x4(af[mt], a_base + (a_lrow + mt * 16) * 80 + kb + a_koff);
            uint32_t bf[4][2];
#pragma unroll
            for (int pr = 0; pr < 2; pr++) {
                uint32_t t4[4];
                ldsm_x4(t4, b_base + (b_lrow + pr * 16) * 80 + kb + b_koff);
                bf[pr * 2 + 0][0] = t4[0]; bf[pr * 2 + 0][1] = t4[1];
                bf[pr * 2 + 1][0] = t4[2]; bf[pr * 2 + 1][1] = t4[3];
            }
#pragma unroll
            for (int mt = 0; mt < 4; mt++)
#pragma unroll
                for (int nt = 0; nt < 4; nt++)
                    mma_bf16(acc[mt][nt], af[mt], bf[nt]);
        }
    }

    // epilogue
#pragma unroll
    for (int mt = 0; mt < 4; mt++) {
        int r0 = row0 + wm + mt * 16 + g;
#pragma unroll
        for (int nt = 0; nt < 4; nt++) {
            int col = col0 + wn + nt * 8 + 2 * qc;
            float b0 = bias[col], b1 = bias[col + 1];
#pragma unroll
            for (int half = 0; half < 2; half++) {
                int rrow = r0 + half * 8;
                if (rrow < M) {
                    float vx = acc[mt][nt][half * 2 + 0] + b0;
                    float vy = acc[mt][nt][half * 2 + 1] + b1;
                    if (RELU) { vx = fmaxf(vx, 0.f); vy = fmaxf(vy, 0.f); }
                    if (OUTBF16) {
                        __nv_bfloat162 v2 = __floats2bfloat162_rn(vx, vy);
                        *(__nv_bfloat162*)((__nv_bfloat16*)Cv + (size_t)rrow * N + col) = v2;
                    } else {
                        *(float2*)((float*)Cv + (size_t)rrow * N + col) = make_float2(vx, vy);
                    }
                }
            }
        }
    }
}

// =====================================================================
// Fused transposes of all 4 weight matrices -> bf16, K-major.
// =====================================================================
__global__ void transpose_all_kernel(const float* __restrict__ Wv, const float* __restrict__ Wo,
                                     const float* __restrict__ W1, const float* __restrict__ W2,
                                     __nv_bfloat16* __restrict__ WvT, __nv_bfloat16* __restrict__ WoT,
                                     __nv_bfloat16* __restrict__ W1T, __nv_bfloat16* __restrict__ W2T)
{
    __shared__ float t[32][33];
    int z = blockIdx.z;
    const float* src; __nv_bfloat16* dst; int R, C;
    if (z == 0)      { src = Wv; dst = WvT; R = 256;  C = 256;  }
    else if (z == 1) { src = Wo; dst = WoT; R = 256;  C = 256;  }
    else if (z == 2) { src = W1; dst = W1T; R = 256;  C = 1024; }
    else             { src = W2; dst = W2T; R = 1024; C = 256;  }

    int bx = blockIdx.x * 32, by = blockIdx.y * 32;
    if (bx >= C || by >= R) return;
#pragma unroll
    for (int i = 0; i < 32; i += 8) {
        int r = by + threadIdx.y + i, c = bx + threadIdx.x;
        if (r < R && c < C) t[threadIdx.y + i][threadIdx.x] = src[(size_t)r * C + c];
    }
    __syncthreads();
#pragma unroll
    for (int i = 0; i < 32; i += 8) {
        int r = bx + threadIdx.y + i, c = by + threadIdx.x;
        if (r < C && c < R) dst[(size_t)r * R + c] = __float2bfloat16(t[threadIdx.x][threadIdx.y + i]);
    }
}

// =====================================================================
// fp32 -> bf16 bulk convert (for src)
// =====================================================================
__global__ void f2bf_kernel(const float4* __restrict__ in, __nv_bfloat162* __restrict__ out, int n4)
{
    int i = blockIdx.x * blockDim.x + threadIdx.x;
    if (i < n4) {
        float4 v = in[i];
        out[2 * i + 0] = __floats2bfloat162_rn(v.x, v.y);
        out[2 * i + 1] = __floats2bfloat162_rn(v.z, v.w);
    }
}

// =====================================================================
// Top-4 over 7x7 window of (w*mask + b), pad=0, stable ties (lower idx).
// =====================================================================
__global__ void topk_kernel(const float* __restrict__ m0, const float* __restrict__ m1,
                            const float* __restrict__ m2, const float* __restrict__ m3,
                            const float* __restrict__ pmw, const float* __restrict__ pmb)
{
    int t = blockIdx.x * blockDim.x + threadIdx.x;
    if (t >= MROWS * NH) return;
    int h = t % NH;
    int r = t / NH;
    int q = r % LEN;
    int b = r / LEN;

    int l, Wl, s0;
    const float* mk;
    if (q < 8464)        { l = 0; Wl = 92; s0 = 0;     mk = m0; }
    else if (q < 10580)  { l = 1; Wl = 46; s0 = 8464;  mk = m1; }
    else if (q < 11109)  { l = 2; Wl = 23; s0 = 10580; mk = m2; }
    else                 { l = 3; Wl = 12; s0 = 11109; mk = m3; }
    int Hl = Wl;
    int pos = q - s0;
    int y = pos / Wl, x = pos % Wl;

    float w  = pmw[l * NH + h];
    float bb = pmb[l * NH + h];
    const float* mb = mk + (size_t)b * Hl * Wl;

    float tv[4] = {-1e30f, -1e30f, -1e30f, -1e30f};
    int   ti[4] = {0, 0, 0, 0};

    for (int i = 0; i < 7; i++) {
        int yy = y + i - 3;
        for (int j = 0; j < 7; j++) {
            int xx = x + j - 3;
            float val = 0.0f;
            if (yy >= 0 && yy < Hl && xx >= 0 && xx < Wl)
                val = fmaf(mb[yy * Wl + xx], w, bb);
            if (val > tv[3]) {
                int k = i * 7 + j;
                tv[3] = val; ti[3] = k;
                if (tv[3] > tv[2]) { float fv = tv[2]; tv[2] = tv[3]; tv[3] = fv; int iv = ti[2]; ti[2] = ti[3]; ti[3] = iv; }
                if (tv[2] > tv[1]) { float fv = tv[1]; tv[1] = tv[2]; tv[2] = fv; int iv = ti[1]; ti[1] = ti[2]; ti[2] = iv; }
                if (tv[1] > tv[0]) { float fv = tv[0]; tv[0] = tv[1]; tv[1] = fv; int iv = ti[0]; ti[0] = ti[1]; ti[1] = iv; }
            }
        }
    }

    float mx = tv[0];
    float e0 = expf(tv[0] - mx), e1 = expf(tv[1] - mx),
          e2 = expf(tv[2] - mx), e3 = expf(tv[3] - mx);
    float inv = 1.0f / (4.0f * (e0 + e1 + e2 + e3));

    int base = (r * NH + h) * NP;
    float ee[4] = {e0, e1, e2, e3};
#pragma unroll
    for (int p = 0; p < 4; p++) {
        g_attw[base + p] = ee[p] * inv;
        g_offs[(size_t)(base + p) * 2 + 0] = (float)(ti[p] % 7 - 3);
        g_offs[(size_t)(base + p) * 2 + 1] = (float)(ti[p] / 7 - 3);
    }
}

// =====================================================================
// Deformable sampling, vectorized: warp = (query, head).
// Scalar phase (lanes 0-15): 16 (level,point) combos -> 4 corners each,
// packed (idx, weight) int2 in smem.
// Gather phase: lane = (corner j = lane/8, channel quad = lane%8);
// per combo: 1 LDS.64 broadcast + 1 LDG.128 + 4 FMA. Cross-corner
// shfl reduce at the end; lanes 0-7 store bf16x4.
// =====================================================================
__global__ void __launch_bounds__(256)
sample_kernel(const float* __restrict__ ref)
{
    __shared__ int2 s_d[8][16][4];   // [head][combo][corner] = (idx, w-bits)

    int r = blockIdx.x;
    int wid = threadIdx.x >> 5, lane = threadIdx.x & 31;
    int b = r / LEN;

    if (lane < 16) {
        const int HsA[4] = {92, 46, 23, 12};
        const int S0A[4] = {0, 8464, 10580, 11109};
        int l = lane >> 2, p = lane & 3;
        int Wi = HsA[l];
        float Wf = (float)Wi;

        float rx = ref[(size_t)(r * NL + l) * 2 + 0];
        float ry = ref[(size_t)(r * NL + l) * 2 + 1];
        int base = (r * NH + wid) * NP + p;
        float wgt = g_attw[base];
        float ox  = g_offs[(size_t)base * 2 + 0];
        float oy  = g_offs[(size_t)base * 2 + 1];

        float locx = rx + ox / Wf;
        float locy = ry + oy / Wf;
        float xf = locx * Wf - 0.5f;
        float yf = locy * Wf - 0.5f;
        float x0f = floorf(xf), y0f = floorf(yf);
        float tx = xf - x0f, ty = yf - y0f;
        int x0 = (int)x0f, y0 = (int)y0f;
        int x1 = x0 + 1,  y1 = y0 + 1;

        float w00 = (1.0f - tx) * (1.0f - ty) * wgt;
        float w01 = tx * (1.0f - ty) * wgt;
        float w10 = (1.0f - tx) * ty * wgt;
        float w11 = tx * ty * wgt;

        bool vx0 = (x0 >= 0) & (x0 < Wi);
        bool vx1 = (x1 >= 0) & (x1 < Wi);
        bool vy0 = (y0 >= 0) & (y0 < Wi);
        bool vy1 = (y1 >= 0) & (y1 < Wi);

        int x0c = min(max(x0, 0), Wi - 1), x1c = min(max(x1, 0), Wi - 1);
        int y0c = min(max(y0, 0), Wi - 1), y1c = min(max(y1, 0), Wi - 1);
        int rb = b * LEN + S0A[l];

        s_d[wid][lane][0] = make_int2(rb + y0c * Wi + x0c, __float_as_int((vy0 & vx0) ? w00 : 0.0f));
        s_d[wid][lane][1] = make_int2(rb + y0c * Wi + x1c, __float_as_int((vy0 & vx1) ? w01 : 0.0f));
        s_d[wid][lane][2] = make_int2(rb + y1c * Wi + x0c, __float_as_int((vy1 & vx0) ? w10 : 0.0f));
        s_d[wid][lane][3] = make_int2(rb + y1c * Wi + x1c, __float_as_int((vy1 & vx1) ? w11 : 0.0f));
    }
    __syncwarp();

    int j  = lane >> 3;      // corner group
    int cq = lane & 7;       // channel quad (4 floats)
    const float* vb = g_value + wid * DH + cq * 4;

    float ax = 0.f, ay = 0.f, az = 0.f, aw = 0.f;
#pragma unroll
    for (int c = 0; c < 16; c++) {
        int2 d = s_d[wid][c][j];
        float w = __int_as_float(d.y);
        float4 v = *(const float4*)(vb + (size_t)d.x * D);
        ax = fmaf(w, v.x, ax);
        ay = fmaf(w, v.y, ay);
        az = fmaf(w, v.z, az);
        aw = fmaf(w, v.w, aw);
    }
#pragma unroll
    for (int o = 8; o <= 16; o <<= 1) {
        ax += __shfl_xor_sync(0xffffffffu, ax, o);
        ay += __shfl_xor_sync(0xffffffffu, ay, o);
        az += __shfl_xor_sync(0xffffffffu, az, o);
        aw += __shfl_xor_sync(0xffffffffu, aw, o);
    }
    if (lane < 8) {
        __nv_bfloat162 p0 = __floats2bfloat162_rn(ax, ay);
        __nv_bfloat162 p1 = __floats2bfloat162_rn(az, aw);
        uint2 st;
        st.x = *(uint32_t*)&p0;
        st.y = *(uint32_t*)&p1;
        *(uint2*)(g_attnb + (size_t)r * D + wid * DH + cq * 4) = st;
    }
}

// =====================================================================
// out = LayerNorm(a + res) * g + b; optionally also write bf16 copy
// =====================================================================
template<int WR>
__global__ void add_ln_kernel(const float* __restrict__ a, const float* __restrict__ res,
                              const float* __restrict__ gg, const float* __restrict__ bb,
                              float* __restrict__ out, __nv_bfloat16* __restrict__ out_r)
{
    int row = blockIdx.x;
    int t = threadIdx.x;
    float v = a[(size_t)row * D + t] + res[(size_t)row * D + t];

    __shared__ float s1[8], s2[8];
    float s = v, u = v * v;
#pragma unroll
    for (int o = 16; o; o >>= 1) {
        s += __shfl_xor_sync(0xffffffffu, s, o);
        u += __shfl_xor_sync(0xffffffffu, u, o);
    }
    if ((t & 31) == 0) { s1[t >> 5] = s; s2[t >> 5] = u; }
    __syncthreads();
    float sum = 0.f, sq = 0.f;
#pragma unroll
    for (int i = 0; i < 8; i++) { sum += s1[i]; sq += s2[i]; }
    float mean = sum * (1.0f / D);
    float var  = sq * (1.0f / D) - mean * mean;
    float rs = rsqrtf(var + 1e-5f);
    float o = (v - mean) * rs * gg[t] + bb[t];
    out[(size_t)row * D + t] = o;
    if (WR) out_r[(size_t)row * D + t] = __float2bfloat16(o);
}

// =====================================================================
extern "C" void kernel_launch(void* const* d_in, const int* in_sizes, int n_in,
                              void* d_out, int out_size)
{
    const float* src  = (const float*)d_in[0];
    const float* ref  = (const float*)d_in[2];
    const float* m0   = (const float*)d_in[4];
    const float* m1   = (const float*)d_in[5];
    const float* m2   = (const float*)d_in[6];
    const float* m3   = (const float*)d_in[7];
    const float* pmw  = (const float*)d_in[10];
    const float* pmb  = (const float*)d_in[11];
    const float* Wv   = (const float*)d_in[12];
    const float* bv   = (const float*)d_in[13];
    const float* Wo   = (const float*)d_in[14];
    const float* bo   = (const float*)d_in[15];
    const float* ln1g = (const float*)d_in[16];
    const float* ln1b = (const float*)d_in[17];
    const float* W1   = (const float*)d_in[18];
    const float* b1   = (const float*)d_in[19];
    const float* W2   = (const float*)d_in[20];
    const float* b2   = (const float*)d_in[21];
    const float* ln2g = (const float*)d_in[22];
    const float* ln2b = (const float*)d_in[23];
    float* out = (float*)d_out;

    float *pv, *ptmp, *px;
    __nv_bfloat16 *psb, *pab, *pxr, *ph, *pWvT, *pWoT, *pW1T, *pW2T;
    cudaGetSymbolAddress((void**)&pv,   g_value);
    cudaGetSymbolAddress((void**)&psb,  g_srcb);
    cudaGetSymbolAddress((void**)&pab,  g_attnb);
    cudaGetSymbolAddress((void**)&ptmp, g_tmp);
    cudaGetSymbolAddress((void**)&px,   g_x);
    cudaGetSymbolAddress((void**)&pxr,  g_xr);
    cudaGetSymbolAddress((void**)&ph,   g_hid);
    cudaGetSymbolAddress((void**)&pWvT, g_WvT);
    cudaGetSymbolAddress((void**)&pWoT, g_WoT);
    cudaGetSymbolAddress((void**)&pW1T, g_W1T);
    cudaGetSymbolAddress((void**)&pW2T, g_W2T);

    cudaFuncSetAttribute((const void*)gemm_bf<0,0>, cudaFuncAttributeMaxDynamicSharedMemorySize, GEMM_SMEM);
    cudaFuncSetAttribute((const void*)gemm_bf<1,1>, cudaFuncAttributeMaxDynamicSharedMemorySize, GEMM_SMEM);

    const int MB = (MROWS + 127) / 128;   // 176

    // 0. weight transposes -> bf16 (one launch) + src -> bf16
    transpose_all_kernel<<<dim3(32, 32, 4), dim3(32, 8)>>>(Wv, Wo, W1, W2,
                                                           pWvT, pWoT, pW1T, pW2T);
    {
        int n4 = MROWS * D / 4;
        f2bf_kernel<<<(n4 + 255) / 256, 256>>>((const float4*)src, (__nv_bfloat162*)psb, n4);
    }

    // 1. top-k offsets + attention weights
    topk_kernel<<<(MROWS * NH + 255) / 256, 256>>>(m0, m1, m2, m3, pmw, pmb);

    // 2. value = src @ Wv + bv  (fp32 out for sampler)
    gemm_bf<0,0><<<dim3(2, MB), 256, GEMM_SMEM>>>(psb, pWvT, bv, pv, MROWS, 256, 256);

    // 3. deformable bilinear sampling -> bf16 attnout
    sample_kernel<<<MROWS, 256>>>(ref);

    // 4. attn_out = attnout @ Wo + bo  (fp32 out)
    gemm_bf<0,0><<<dim3(2, MB), 256, GEMM_SMEM>>>(pab, pWoT, bo, ptmp, MROWS, 256, 256);

    // 5. x = LN(src + attn_out); fp32 x + bf16 copy
    add_ln_kernel<1><<<MROWS, 256>>>(ptmp, src, ln1g, ln1b, px, pxr);

    // 6. hid = relu(x @ W1 + b1) -> bf16
    gemm_bf<1,1><<<dim3(8, MB), 256, GEMM_SMEM>>>(pxr, pW1T, b1, ph, MROWS, 1024, 256);

    // 7. y = hid @ W2 + b2  (fp32 out)
    gemm_bf<0,0><<<dim3(2, MB), 256, GEMM_SMEM>>>(ph, pW2T, b2, ptmp, MROWS, 256, 1024);

    // 8. out = LN(x + y)
    add_ln_kernel<0><<<MROWS, 256>>>(ptmp, px, ln2g, ln2b, out, nullptr);
}

// round 9
// speedup vs baseline: 4.7961x; 1.1112x over previous
#include <cuda_runtime.h>
#include <cuda_bf16.h>
#include <cstdint>
#include <math.h>

#define BS   2
#define LEN  11253
#define MROWS (BS*LEN)   // 22506
#define D    256
#define NH   8
#define NP   4
#define NL   4
#define DH   32
#define DFF  1024

// ---- scratch (device globals; no allocation allowed) ----
__device__ __nv_bfloat16  g_valb   [(size_t)MROWS * D];
__device__ __nv_bfloat16  g_srcb   [(size_t)MROWS * D];
__device__ __nv_bfloat16  g_attnb  [(size_t)MROWS * D];
__device__ float          g_tmp    [(size_t)MROWS * D];
__device__ float          g_x      [(size_t)MROWS * D];
__device__ __nv_bfloat16  g_xr     [(size_t)MROWS * D];
__device__ __nv_bfloat16  g_hid    [(size_t)MROWS * DFF];
__device__ float          g_attw   [(size_t)MROWS * NH * NP];
__device__ float          g_offs   [(size_t)MROWS * NH * NP * 2];
__device__ __nv_bfloat16  g_WvT    [D * D];
__device__ __nv_bfloat16  g_WoT    [D * D];
__device__ __nv_bfloat16  g_W1T    [DFF * D];
__device__ __nv_bfloat16  g_W2T    [D * DFF];

// =====================================================================
// helpers
// =====================================================================
__device__ __forceinline__ void mma_bf16(float* d, const uint32_t* a, const uint32_t* b) {
    asm volatile(
        "mma.sync.aligned.m16n8k16.row.col.f32.bf16.bf16.f32 "
        "{%0,%1,%2,%3}, {%4,%5,%6,%7}, {%8,%9}, {%0,%1,%2,%3};"
        : "+f"(d[0]), "+f"(d[1]), "+f"(d[2]), "+f"(d[3])
        : "r"(a[0]), "r"(a[1]), "r"(a[2]), "r"(a[3]), "r"(b[0]), "r"(b[1]));
}
__device__ __forceinline__ void ldsm_x4(uint32_t* r, uint32_t addr) {
    asm volatile("ldmatrix.sync.aligned.m8n8.x4.shared.b16 {%0,%1,%2,%3}, [%4];"
        : "=r"(r[0]), "=r"(r[1]), "=r"(r[2]), "=r"(r[3]) : "r"(addr));
}

// =====================================================================
// BF16 tensor-core GEMM: C[M,N] = A[M,K] @ BT[N,K]^T + bias (opt relu)
// 128x128 CTA tile, BK=32, 3-stage cp.async, 8 warps (2m x 4n),
// 64x32 warp tile, ldmatrix fragment loads, 2 CTAs/SM.
// =====================================================================
#define SSTR        40                    // bf16 units per smem row
#define TILE_B      (128*SSTR*2)          // 10240 bytes per operand tile
#define STAGE_B     (2*TILE_B)            // 20480
#define GEMM_SMEM   (3*STAGE_B)           // 61440

template<int RELU, int OUTBF16>
__global__ void __launch_bounds__(256, 2)
gemm_bf(const __nv_bfloat16* __restrict__ A, const __nv_bfloat16* __restrict__ BT,
        const float* __restrict__ bias, void* __restrict__ Cv,
        int M, int N, int K)
{
    extern __shared__ __align__(16) char smem[];
    int tid = threadIdx.x, wid = tid >> 5, lane = tid & 31;
    int g = lane >> 2, qc = lane & 3;
    int row0 = blockIdx.y * 128, col0 = blockIdx.x * 128;
    int wm = (wid & 1) * 64, wn = (wid >> 1) * 32;

    uint32_t smem_u;
    asm("{ .reg .u64 t; cvta.to.shared.u64 t, %1; cvt.u32.u64 %0, t; }" : "=r"(smem_u) : "l"(smem));

    const int NC = K >> 5;

    auto load_chunk = [&](int c) {
        if (c >= NC) { asm volatile("cp.async.commit_group;"); return; }
        uint32_t a_st = smem_u + (c % 3) * STAGE_B;
        uint32_t b_st = a_st + TILE_B;
        int k0 = c * 32;
        const __nv_bfloat16* Ab = A + (size_t)row0 * K + k0;
        const __nv_bfloat16* Bb = BT + (size_t)col0 * K + k0;
#pragma unroll
        for (int i = 0; i < 2; i++) {
            int f4 = tid + i * 256;
            int r = f4 >> 2, seg = f4 & 3;
            uint32_t off = (uint32_t)(r * (SSTR * 2) + seg * 16);
            uint32_t nbytes = (row0 + r < M) ? 16u : 0u;
            asm volatile("cp.async.cg.shared.global [%0], [%1], 16, %2;"
                :: "r"(a_st + off), "l"(Ab + (size_t)r * K + seg * 8), "r"(nbytes));
            asm volatile("cp.async.cg.shared.global [%0], [%1], 16;"
                :: "r"(b_st + off), "l"(Bb + (size_t)r * K + seg * 8));
        }
        asm volatile("cp.async.commit_group;");
    };

    float acc[4][4][4];
#pragma unroll
    for (int mt = 0; mt < 4; mt++)
#pragma unroll
        for (int nt = 0; nt < 4; nt++)
#pragma unroll
            for (int i = 0; i < 4; i++) acc[mt][nt][i] = 0.0f;

    int sub = lane >> 3, rr = lane & 7;
    uint32_t a_lrow = (uint32_t)(wm + (sub & 1) * 8 + rr);
    uint32_t a_koff = (uint32_t)((sub >> 1) * 16);
    uint32_t b_lrow = (uint32_t)(wn + (sub >> 1) * 8 + rr);
    uint32_t b_koff = (uint32_t)((sub & 1) * 16);

    load_chunk(0);
    load_chunk(1);

    for (int c = 0; c < NC; c++) {
        asm volatile("cp.async.wait_group 1;");
        __syncthreads();
        load_chunk(c + 2);

        uint32_t a_base = smem_u + (c % 3) * STAGE_B;
        uint32_t b_base = a_base + TILE_B;
#pragma unroll
        for (int ks = 0; ks < 2; ks++) {
            uint32_t kb = (uint32_t)(ks * 32);
            uint32_t af[4][4];
#pragma unroll
            for (int mt = 0; mt < 4; mt++)
                ldsm_x4(af[mt], a_base + (a_lrow + mt * 16) * 80 + kb + a_koff);
            uint32_t bf[4][2];
#pragma unroll
            for (int pr = 0; pr < 2; pr++) {
                uint32_t t4[4];
                ldsm_x4(t4, b_base + (b_lrow + pr * 16) * 80 + kb + b_koff);
                bf[pr * 2 + 0][0] = t4[0]; bf[pr * 2 + 0][1] = t4[1];
                bf[pr * 2 + 1][0] = t4[2]; bf[pr * 2 + 1][1] = t4[3];
            }
#pragma unroll
            for (int mt = 0; mt < 4; mt++)
#pragma unroll
                for (int nt = 0; nt < 4; nt++)
                    mma_bf16(acc[mt][nt], af[mt], bf[nt]);
        }
    }

    // epilogue
#pragma unroll
    for (int mt = 0; mt < 4; mt++) {
        int r0 = row0 + wm + mt * 16 + g;
#pragma unroll
        for (int nt = 0; nt < 4; nt++) {
            int col = col0 + wn + nt * 8 + 2 * qc;
            float b0 = bias[col], b1 = bias[col + 1];
#pragma unroll
            for (int half = 0; half < 2; half++) {
                int rrow = r0 + half * 8;
                if (rrow < M) {
                    float vx = acc[mt][nt][half * 2 + 0] + b0;
                    float vy = acc[mt][nt][half * 2 + 1] + b1;
                    if (RELU) { vx = fmaxf(vx, 0.f); vy = fmaxf(vy, 0.f); }
                    if (OUTBF16) {
                        __nv_bfloat162 v2 = __floats2bfloat162_rn(vx, vy);
                        *(__nv_bfloat162*)((__nv_bfloat16*)Cv + (size_t)rrow * N + col) = v2;
                    } else {
                        *(float2*)((float*)Cv + (size_t)rrow * N + col) = make_float2(vx, vy);
                    }
                }
            }
        }
    }
}

// =====================================================================
// Fused prep: weight transposes -> bf16 (blocks 0-639),
// src -> bf16 (blocks 640-6266), topk (blocks 6267-6970).
// =====================================================================
#define PREP_T_BLK   640
#define PREP_F_BLK   5627     // ceil(MROWS*D/4 / 256)
#define PREP_K_BLK   704      // ceil(MROWS*NH / 256)
#define PREP_BLOCKS  (PREP_T_BLK + PREP_F_BLK + PREP_K_BLK)

__global__ void __launch_bounds__(256)
prep_kernel(const float* __restrict__ src,
            const float* __restrict__ Wv, const float* __restrict__ Wo,
            const float* __restrict__ W1, const float* __restrict__ W2,
            const float* __restrict__ m0, const float* __restrict__ m1,
            const float* __restrict__ m2, const float* __restrict__ m3,
            const float* __restrict__ pmw, const float* __restrict__ pmb,
            __nv_bfloat16* __restrict__ WvT, __nv_bfloat16* __restrict__ WoT,
            __nv_bfloat16* __restrict__ W1T, __nv_bfloat16* __restrict__ W2T,
            __nv_bfloat16* __restrict__ srcb)
{
    int bid = blockIdx.x;
    int tid = threadIdx.x;

    if (bid < PREP_T_BLK) {
        // ---- transpose branch ----
        __shared__ float t[32][33];
        const float* s; __nv_bfloat16* dst; int R, C, bx, by;
        if (bid < 64)       { s = Wv; dst = WvT; R = 256;  C = 256;  int u = bid;       bx = u & 7;  by = u >> 3; }
        else if (bid < 128) { s = Wo; dst = WoT; R = 256;  C = 256;  int u = bid - 64;  bx = u & 7;  by = u >> 3; }
        else if (bid < 384) { s = W1; dst = W1T; R = 256;  C = 1024; int u = bid - 128; bx = u & 31; by = u >> 5; }
        else                { s = W2; dst = W2T; R = 1024; C = 256;  int u = bid - 384; bx = u & 7;  by = u >> 3; }
        bx *= 32; by *= 32;
        int tx = tid & 31, ty = tid >> 5;
#pragma unroll
        for (int i = 0; i < 32; i += 8)
            t[ty + i][tx] = s[(size_t)(by + ty + i) * C + bx + tx];
        __syncthreads();
#pragma unroll
        for (int i = 0; i < 32; i += 8)
            dst[(size_t)(bx + ty + i) * R + by + tx] = __float2bfloat16(t[tx][ty + i]);
        return;
    }
    if (bid < PREP_T_BLK + PREP_F_BLK) {
        // ---- src -> bf16 branch ----
        int i = (bid - PREP_T_BLK) * 256 + tid;
        const int n4 = MROWS * D / 4;
        if (i < n4) {
            float4 v = ((const float4*)src)[i];
            ((__nv_bfloat162*)srcb)[2 * i + 0] = __floats2bfloat162_rn(v.x, v.y);
            ((__nv_bfloat162*)srcb)[2 * i + 1] = __floats2bfloat162_rn(v.z, v.w);
        }
        return;
    }
    // ---- topk branch ----
    int t = (bid - PREP_T_BLK - PREP_F_BLK) * 256 + tid;
    if (t >= MROWS * NH) return;
    int h = t % NH;
    int r = t / NH;
    int q = r % LEN;
    int b = r / LEN;

    int l, Wl, s0;
    const float* mk;
    if (q < 8464)        { l = 0; Wl = 92; s0 = 0;     mk = m0; }
    else if (q < 10580)  { l = 1; Wl = 46; s0 = 8464;  mk = m1; }
    else if (q < 11109)  { l = 2; Wl = 23; s0 = 10580; mk = m2; }
    else                 { l = 3; Wl = 12; s0 = 11109; mk = m3; }
    int Hl = Wl;
    int pos = q - s0;
    int y = pos / Wl, x = pos % Wl;

    float w  = pmw[l * NH + h];
    float bb = pmb[l * NH + h];
    const float* mb = mk + (size_t)b * Hl * Wl;

    float tv[4] = {-1e30f, -1e30f, -1e30f, -1e30f};
    int   ti[4] = {0, 0, 0, 0};

    for (int i = 0; i < 7; i++) {
        int yy = y + i - 3;
        for (int j = 0; j < 7; j++) {
            int xx = x + j - 3;
            float val = 0.0f;
            if (yy >= 0 && yy < Hl && xx >= 0 && xx < Wl)
                val = fmaf(mb[yy * Wl + xx], w, bb);
            if (val > tv[3]) {
                int k = i * 7 + j;
                tv[3] = val; ti[3] = k;
                if (tv[3] > tv[2]) { float fv = tv[2]; tv[2] = tv[3]; tv[3] = fv; int iv = ti[2]; ti[2] = ti[3]; ti[3] = iv; }
                if (tv[2] > tv[1]) { float fv = tv[1]; tv[1] = tv[2]; tv[2] = fv; int iv = ti[1]; ti[1] = ti[2]; ti[2] = iv; }
                if (tv[1] > tv[0]) { float fv = tv[0]; tv[0] = tv[1]; tv[1] = fv; int iv = ti[0]; ti[0] = ti[1]; ti[1] = iv; }
            }
        }
    }

    float mx = tv[0];
    float e0 = expf(tv[0] - mx), e1 = expf(tv[1] - mx),
          e2 = expf(tv[2] - mx), e3 = expf(tv[3] - mx);
    float inv = 1.0f / (4.0f * (e0 + e1 + e2 + e3));

    int base = (r * NH + h) * NP;
    float ee[4] = {e0, e1, e2, e3};
#pragma unroll
    for (int p = 0; p < 4; p++) {
        g_attw[base + p] = ee[p] * inv;
        g_offs[(size_t)(base + p) * 2 + 0] = (float)(ti[p] % 7 - 3);
        g_offs[(size_t)(base + p) * 2 + 1] = (float)(ti[p] / 7 - 3);
    }
}

// =====================================================================
// Deformable sampling: warp = (query, head), bf16 value gathers.
// Scalar phase (lanes 0-15): 16 combos -> (idx, weight) per corner.
// Gather: lane = (corner = lane/8, channel quad = lane%8);
// per combo: LDS.64 broadcast + LDG.64 (4 bf16) + cvt + 4 FMA.
// =====================================================================
__global__ void __launch_bounds__(256)
sample_kernel(const float* __restrict__ ref)
{
    __shared__ int2 s_d[8][16][4];

    int r = blockIdx.x;
    int wid = threadIdx.x >> 5, lane = threadIdx.x & 31;
    int b = r / LEN;

    if (lane < 16) {
        const int HsA[4] = {92, 46, 23, 12};
        const int S0A[4] = {0, 8464, 10580, 11109};
        int l = lane >> 2, p = lane & 3;
        int Wi = HsA[l];
        float Wf = (float)Wi;

        float rx = ref[(size_t)(r * NL + l) * 2 + 0];
        float ry = ref[(size_t)(r * NL + l) * 2 + 1];
        int base = (r * NH + wid) * NP + p;
        float wgt = g_attw[base];
        float ox  = g_offs[(size_t)base * 2 + 0];
        float oy  = g_offs[(size_t)base * 2 + 1];

        float locx = rx + ox / Wf;
        float locy = ry + oy / Wf;
        float xf = locx * Wf - 0.5f;
        float yf = locy * Wf - 0.5f;
        float x0f = floorf(xf), y0f = floorf(yf);
        float tx = xf - x0f, ty = yf - y0f;
        int x0 = (int)x0f, y0 = (int)y0f;
        int x1 = x0 + 1,  y1 = y0 + 1;

        float w00 = (1.0f - tx) * (1.0f - ty) * wgt;
        float w01 = tx * (1.0f - ty) * wgt;
        float w10 = (1.0f - tx) * ty * wgt;
        float w11 = tx * ty * wgt;

        bool vx0 = (x0 >= 0) & (x0 < Wi);
        bool vx1 = (x1 >= 0) & (x1 < Wi);
        bool vy0 = (y0 >= 0) & (y0 < Wi);
        bool vy1 = (y1 >= 0) & (y1 < Wi);

        int x0c = min(max(x0, 0), Wi - 1), x1c = min(max(x1, 0), Wi - 1);
        int y0c = min(max(y0, 0), Wi - 1), y1c = min(max(y1, 0), Wi - 1);
        int rb = b * LEN + S0A[l];

        s_d[wid][lane][0] = make_int2(rb + y0c * Wi + x0c, __float_as_int((vy0 & vx0) ? w00 : 0.0f));
        s_d[wid][lane][1] = make_int2(rb + y0c * Wi + x1c, __float_as_int((vy0 & vx1) ? w01 : 0.0f));
        s_d[wid][lane][2] = make_int2(rb + y1c * Wi + x0c, __float_as_int((vy1 & vx0) ? w10 : 0.0f));
        s_d[wid][lane][3] = make_int2(rb + y1c * Wi + x1c, __float_as_int((vy1 & vx1) ? w11 : 0.0f));
    }
    __syncwarp();

    int j  = lane >> 3;      // corner group
    int cq = lane & 7;       // channel quad (4 bf16)
    const __nv_bfloat16* vb = g_valb + wid * DH + cq * 4;

    float ax = 0.f, ay = 0.f, az = 0.f, aw = 0.f;
#pragma unroll
    for (int c = 0; c < 16; c++) {
        int2 d = s_d[wid][c][j];
        float w = __int_as_float(d.y);
        uint2 raw = *(const uint2*)(vb + (size_t)d.x * D);
        float2 f0 = __bfloat1622float2(*(__nv_bfloat162*)&raw.x);
        float2 f1 = __bfloat1622float2(*(__nv_bfloat162*)&raw.y);
        ax = fmaf(w, f0.x, ax);
        ay = fmaf(w, f0.y, ay);
        az = fmaf(w, f1.x, az);
        aw = fmaf(w, f1.y, aw);
    }
#pragma unroll
    for (int o = 8; o <= 16; o <<= 1) {
        ax += __shfl_xor_sync(0xffffffffu, ax, o);
        ay += __shfl_xor_sync(0xffffffffu, ay, o);
        az += __shfl_xor_sync(0xffffffffu, az, o);
        aw += __shfl_xor_sync(0xffffffffu, aw, o);
    }
    if (lane < 8) {
        __nv_bfloat162 p0 = __floats2bfloat162_rn(ax, ay);
        __nv_bfloat162 p1 = __floats2bfloat162_rn(az, aw);
        uint2 st;
        st.x = *(uint32_t*)&p0;
        st.y = *(uint32_t*)&p1;
        *(uint2*)(g_attnb + (size_t)r * D + wid * DH + cq * 4) = st;
    }
}

// =====================================================================
// out = LayerNorm(a + res) * g + b, float4-vectorized, 4 rows/block.
// =====================================================================
template<int WR>
__global__ void __launch_bounds__(256)
add_ln_kernel(const float4* __restrict__ a, const float4* __restrict__ res,
              const float4* __restrict__ gg, const float4* __restrict__ bb,
              float4* __restrict__ out, __nv_bfloat16* __restrict__ out_r)
{
    int tid = threadIdx.x;
    int rl = tid >> 6;           // row within block
    int t  = tid & 63;           // float4 index within row
    int row = blockIdx.x * 4 + rl;
    bool ok = row < MROWS;
    size_t idx = (size_t)row * 64 + t;

    float4 v = make_float4(0.f, 0.f, 0.f, 0.f);
    if (ok) {
        float4 va = a[idx], vr = res[idx];
        v = make_float4(va.x + vr.x, va.y + vr.y, va.z + vr.z, va.w + vr.w);
    }
    float s = v.x + v.y + v.z + v.w;
    float u = v.x * v.x + v.y * v.y + v.z * v.z + v.w * v.w;
#pragma unroll
    for (int o = 16; o; o >>= 1) {
        s += __shfl_xor_sync(0xffffffffu, s, o);
        u += __shfl_xor_sync(0xffffffffu, u, o);
    }
    __shared__ float s1[8], s2[8];
    int w = tid >> 5;
    if ((tid & 31) == 0) { s1[w] = s; s2[w] = u; }
    __syncthreads();
    float sum = s1[rl * 2] + s1[rl * 2 + 1];
    float sq  = s2[rl * 2] + s2[rl * 2 + 1];
    float mean = sum * (1.0f / D);
    float var  = sq * (1.0f / D) - mean * mean;
    float rs = rsqrtf(var + 1e-5f);

    if (ok) {
        float4 g4 = gg[t], b4 = bb[t];
        float4 o;
        o.x = (v.x - mean) * rs * g4.x + b4.x;
        o.y = (v.y - mean) * rs * g4.y + b4.y;
        o.z = (v.z - mean) * rs * g4.z + b4.z;
        o.w = (v.w - mean) * rs * g4.w + b4.w;
        out[idx] = o;
        if (WR) {
            __nv_bfloat162 p0 = __floats2bfloat162_rn(o.x, o.y);
            __nv_bfloat162 p1 = __floats2bfloat162_rn(o.z, o.w);
            uint2 st;
            st.x = *(uint32_t*)&p0;
            st.y = *(uint32_t*)&p1;
            *(uint2*)(out_r + idx * 4) = st;
        }
    }
}

// =====================================================================
extern "C" void kernel_launch(void* const* d_in, const int* in_sizes, int n_in,
                              void* d_out, int out_size)
{
    const float* src  = (const float*)d_in[0];
    const float* ref  = (const float*)d_in[2];
    const float* m0   = (const float*)d_in[4];
    const float* m1   = (const float*)d_in[5];
    const float* m2   = (const float*)d_in[6];
    const float* m3   = (const float*)d_in[7];
    const float* pmw  = (const float*)d_in[10];
    const float* pmb  = (const float*)d_in[11];
    const float* Wv   = (const float*)d_in[12];
    const float* bv   = (const float*)d_in[13];
    const float* Wo   = (const float*)d_in[14];
    const float* bo   = (const float*)d_in[15];
    const float* ln1g = (const float*)d_in[16];
    const float* ln1b = (const float*)d_in[17];
    const float* W1   = (const float*)d_in[18];
    const float* b1   = (const float*)d_in[19];
    const float* W2   = (const float*)d_in[20];
    const float* b2   = (const float*)d_in[21];
    const float* ln2g = (const float*)d_in[22];
    const float* ln2b = (const float*)d_in[23];
    float* out = (float*)d_out;

    float *ptmp, *px;
    __nv_bfloat16 *pvb, *psb, *pab, *pxr, *ph, *pWvT, *pWoT, *pW1T, *pW2T;
    cudaGetSymbolAddress((void**)&pvb,  g_valb);
    cudaGetSymbolAddress((void**)&psb,  g_srcb);
    cudaGetSymbolAddress((void**)&pab,  g_attnb);
    cudaGetSymbolAddress((void**)&ptmp, g_tmp);
    cudaGetSymbolAddress((void**)&px,   g_x);
    cudaGetSymbolAddress((void**)&pxr,  g_xr);
    cudaGetSymbolAddress((void**)&ph,   g_hid);
    cudaGetSymbolAddress((void**)&pWvT, g_WvT);
    cudaGetSymbolAddress((void**)&pWoT, g_WoT);
    cudaGetSymbolAddress((void**)&pW1T, g_W1T);
    cudaGetSymbolAddress((void**)&pW2T, g_W2T);

    cudaFuncSetAttribute((const void*)gemm_bf<0,0>, cudaFuncAttributeMaxDynamicSharedMemorySize, GEMM_SMEM);
    cudaFuncSetAttribute((const void*)gemm_bf<0,1>, cudaFuncAttributeMaxDynamicSharedMemorySize, GEMM_SMEM);
    cudaFuncSetAttribute((const void*)gemm_bf<1,1>, cudaFuncAttributeMaxDynamicSharedMemorySize, GEMM_SMEM);

    const int MB = (MROWS + 127) / 128;   // 176
    const int LNB = (MROWS + 3) / 4;      // 5627

    // 0. fused prep: weight transposes + src->bf16 + topk
    prep_kernel<<<PREP_BLOCKS, 256>>>(src, Wv, Wo, W1, W2, m0, m1, m2, m3,
                                      pmw, pmb, pWvT, pWoT, pW1T, pW2T, psb);

    // 1. value = src @ Wv + bv  -> bf16
    gemm_bf<0,1><<<dim3(2, MB), 256, GEMM_SMEM>>>(psb, pWvT, bv, pvb, MROWS, 256, 256);

    // 2. deformable bilinear sampling -> bf16 attnout
    sample_kernel<<<MROWS, 256>>>(ref);

    // 3. attn_out = attnout @ Wo + bo  (fp32 out)
    gemm_bf<0,0><<<dim3(2, MB), 256, GEMM_SMEM>>>(pab, pWoT, bo, ptmp, MROWS, 256, 256);

    // 4. x = LN(src + attn_out); fp32 x + bf16 copy
    add_ln_kernel<1><<<LNB, 256>>>((const float4*)ptmp, (const float4*)src,
                                   (const float4*)ln1g, (const float4*)ln1b,
                                   (float4*)px, pxr);

    // 5. hid = relu(x @ W1 + b1) -> bf16
    gemm_bf<1,1><<<dim3(8, MB), 256, GEMM_SMEM>>>(pxr, pW1T, b1, ph, MROWS, 1024, 256);

    // 6. y = hid @ W2 + b2  (fp32 out)
    gemm_bf<0,0><<<dim3(2, MB), 256, GEMM_SMEM>>>(ph, pW2T, b2, ptmp, MROWS, 256, 1024);

    // 7. out = LN(x + y)
    add_ln_kernel<0><<<LNB, 256>>>((const float4*)ptmp, (const float4*)px,
                                   (const float4*)ln2g, (const float4*)ln2b,
                                   (float4*)out, nullptr);
}